// round 5
// baseline (speedup 1.0000x reference)
#include <cuda_runtime.h>
#include <cuda_bf16.h>
#include <math.h>

// Problem constants
#define SQ   2048          // sequence length (= M = N = K of all GEMMs)
#define EMB  2048
#define NH   16            // output heads
#define HD   64            // differential head dim
#define VD   128           // value head dim = 2*HD

// 0.8 - 0.6*exp(-0.3*12) as a compile-time literal (usable in device code)
#define LAMBDA_INIT_F 0.7836057665316245f

// ---------------------------------------------------------------------------
// Scratch (static __device__ allocations only — no cudaMalloc allowed)
// ---------------------------------------------------------------------------
__device__ float g_Q[SQ * EMB];
__device__ float g_K[SQ * EMB];
__device__ float g_V[SQ * EMB];
__device__ float g_A[SQ * EMB];   // post-attention, post-RMSNorm activations
__device__ float g_lam;           // lambda_full

// ---------------------------------------------------------------------------
// lambda_full = exp(sum lq1*lk1) - exp(sum lq2*lk2) + LAMBDA_INIT
// ---------------------------------------------------------------------------
__global__ void lam_kernel(const float* __restrict__ lq1, const float* __restrict__ lk1,
                           const float* __restrict__ lq2, const float* __restrict__ lk2)
{
    int t = threadIdx.x;   // 32 threads
    float a = lq1[t] * lk1[t] + lq1[t + 32] * lk1[t + 32];
    float b = lq2[t] * lk2[t] + lq2[t + 32] * lk2[t + 32];
    #pragma unroll
    for (int o = 16; o; o >>= 1) {
        a += __shfl_xor_sync(0xffffffffu, a, o);
        b += __shfl_xor_sync(0xffffffffu, b, o);
    }
    if (t == 0) g_lam = expf(a) - expf(b) + LAMBDA_INIT_F;
}

// ---------------------------------------------------------------------------
// SGEMM:  C[i,j] = sum_k A[i,k] * B[j,k]    (A: MxK row-major, B: NxK row-major)
// All dims = 2048.  128x128 tile, BK=16, 256 threads, 8x8 microtile.
// ---------------------------------------------------------------------------
__global__ __launch_bounds__(256) void gemm_nt(const float* __restrict__ A,
                                               const float* __restrict__ B,
                                               float* __restrict__ C)
{
    __shared__ float As[16][132];   // transposed: As[k][m]
    __shared__ float Bs[16][132];   // transposed: Bs[k][n]

    const int tid = threadIdx.x;
    const int bm = blockIdx.y << 7;
    const int bn = blockIdx.x << 7;
    const int tm = (tid >> 4) << 3;     // 0..120
    const int tn = (tid & 15) << 3;     // 0..120

    float acc[8][8];
    #pragma unroll
    for (int i = 0; i < 8; i++)
        #pragma unroll
        for (int j = 0; j < 8; j++) acc[i][j] = 0.f;

    const int lrow = tid >> 2;          // 0..63
    const int lc   = (tid & 3) << 2;    // 0,4,8,12

    for (int k0 = 0; k0 < SQ; k0 += 16) {
        #pragma unroll
        for (int i = 0; i < 2; i++) {
            int row = lrow + (i << 6);
            float4 va = *(const float4*)(A + (size_t)(bm + row) * SQ + k0 + lc);
            As[lc + 0][row] = va.x; As[lc + 1][row] = va.y;
            As[lc + 2][row] = va.z; As[lc + 3][row] = va.w;
            float4 vb = *(const float4*)(B + (size_t)(bn + row) * SQ + k0 + lc);
            Bs[lc + 0][row] = vb.x; Bs[lc + 1][row] = vb.y;
            Bs[lc + 2][row] = vb.z; Bs[lc + 3][row] = vb.w;
        }
        __syncthreads();

        #pragma unroll
        for (int k = 0; k < 16; k++) {
            float ra[8], rb[8];
            #pragma unroll
            for (int i = 0; i < 8; i++) ra[i] = As[k][tm + i];
            #pragma unroll
            for (int j = 0; j < 8; j++) rb[j] = Bs[k][tn + j];
            #pragma unroll
            for (int i = 0; i < 8; i++)
                #pragma unroll
                for (int j = 0; j < 8; j++)
                    acc[i][j] += ra[i] * rb[j];
        }
        __syncthreads();
    }

    #pragma unroll
    for (int i = 0; i < 8; i++) {
        float4* dst = (float4*)(C + (size_t)(bm + tm + i) * SQ + bn + tn);
        dst[0] = make_float4(acc[i][0], acc[i][1], acc[i][2], acc[i][3]);
        dst[1] = make_float4(acc[i][4], acc[i][5], acc[i][6], acc[i][7]);
    }
}

// ---------------------------------------------------------------------------
// Fused differential flash-attention + RMSNorm epilogue.
// Grid: (SQ/32, NH).  Block: 256 threads.
// Each block: 32 query rows of one output head. Streams 32-key tiles.
// Thread (r = tid>>3, cg = tid&7): owns score cols cg+8j (j<4) of both score
// heads, and V cols cg+8i (i<16) of the two running accumulators.
// ---------------------------------------------------------------------------
#define ATT_SMEM_FLOATS (4*32*68 + 32*128 + 2*32*33)
#define ATT_SMEM_BYTES  (ATT_SMEM_FLOATS * 4)

__global__ __launch_bounds__(256) void diffattn_kernel(const float* __restrict__ gw)
{
    extern __shared__ float sm[];
    float* Q1s = sm;                 // [32][68]
    float* Q2s = Q1s + 32 * 68;
    float* K1s = Q2s + 32 * 68;
    float* K2s = K1s + 32 * 68;
    float* Vs  = K2s + 32 * 68;      // [32][128]
    float* Ps1 = Vs  + 32 * 128;     // [32][33]
    float* Ps2 = Ps1 + 32 * 33;

    const int h  = blockIdx.y;
    const int qb = blockIdx.x << 5;
    const int c1 = h << 7;           // score head 2h   -> cols [128h, 128h+64)
    const int c2 = c1 + 64;          // score head 2h+1 -> cols [128h+64, 128h+128)
    const int cv = h << 7;           // value head h    -> cols [128h, 128h+128)

    const int tid = threadIdx.x;
    const int r   = tid >> 3;        // query row within tile (0..31)
    const int cg  = tid & 7;         // column group (0..7)

    // Load Q tiles (scaled by HD^-0.5)
    const float qscale = 0.125f;
    #pragma unroll
    for (int i = 0; i < 2; i++) {
        int idx = tid + (i << 8);
        int row = idx >> 4, c = (idx & 15) << 2;
        float4 a = *(const float4*)&g_Q[(size_t)(qb + row) * EMB + c1 + c];
        float4 b = *(const float4*)&g_Q[(size_t)(qb + row) * EMB + c2 + c];
        *(float4*)&Q1s[row * 68 + c] = make_float4(a.x*qscale, a.y*qscale, a.z*qscale, a.w*qscale);
        *(float4*)&Q2s[row * 68 + c] = make_float4(b.x*qscale, b.y*qscale, b.z*qscale, b.w*qscale);
    }

    float O1[16], O2[16];
    #pragma unroll
    for (int i = 0; i < 16; i++) { O1[i] = 0.f; O2[i] = 0.f; }
    float m1 = -1e30f, l1 = 0.f, m2 = -1e30f, l2 = 0.f;

    for (int kb = 0; kb < SQ; kb += 32) {
        __syncthreads();   // previous tile's compute done before overwrite
        #pragma unroll
        for (int i = 0; i < 2; i++) {
            int idx = tid + (i << 8);
            int row = idx >> 4, c = (idx & 15) << 2;
            *(float4*)&K1s[row * 68 + c] = *(const float4*)&g_K[(size_t)(kb + row) * EMB + c1 + c];
            *(float4*)&K2s[row * 68 + c] = *(const float4*)&g_K[(size_t)(kb + row) * EMB + c2 + c];
        }
        #pragma unroll
        for (int i = 0; i < 4; i++) {
            int idx = tid + (i << 8);
            int row = idx >> 5, c = (idx & 31) << 2;
            *(float4*)&Vs[row * 128 + c] = *(const float4*)&g_V[(size_t)(kb + row) * EMB + cv + c];
        }
        __syncthreads();

        // ---- scores: S1/S2 [32x32] for both score heads ----
        float s1[4] = {0.f,0.f,0.f,0.f}, s2[4] = {0.f,0.f,0.f,0.f};
        #pragma unroll 4
        for (int d = 0; d < 64; d += 4) {
            float4 q1 = *(const float4*)&Q1s[r * 68 + d];
            float4 q2 = *(const float4*)&Q2s[r * 68 + d];
            #pragma unroll
            for (int j = 0; j < 4; j++) {
                int c = cg + (j << 3);
                float4 k1 = *(const float4*)&K1s[c * 68 + d];
                float4 k2 = *(const float4*)&K2s[c * 68 + d];
                s1[j] += q1.x*k1.x + q1.y*k1.y + q1.z*k1.z + q1.w*k1.w;
                s2[j] += q2.x*k2.x + q2.y*k2.y + q2.z*k2.z + q2.w*k2.w;
            }
        }

        // ---- online softmax, head 1 ----
        float mx = fmaxf(fmaxf(s1[0], s1[1]), fmaxf(s1[2], s1[3]));
        mx = fmaxf(mx, __shfl_xor_sync(0xffffffffu, mx, 1));
        mx = fmaxf(mx, __shfl_xor_sync(0xffffffffu, mx, 2));
        mx = fmaxf(mx, __shfl_xor_sync(0xffffffffu, mx, 4));
        float m1n = fmaxf(m1, mx);
        float sc1 = __expf(m1 - m1n);
        float rs1 = 0.f;
        #pragma unroll
        for (int j = 0; j < 4; j++) {
            float p = __expf(s1[j] - m1n);
            rs1 += p;
            Ps1[r * 33 + cg + (j << 3)] = p;
        }
        rs1 += __shfl_xor_sync(0xffffffffu, rs1, 1);
        rs1 += __shfl_xor_sync(0xffffffffu, rs1, 2);
        rs1 += __shfl_xor_sync(0xffffffffu, rs1, 4);
        l1 = l1 * sc1 + rs1;  m1 = m1n;

        // ---- online softmax, head 2 ----
        mx = fmaxf(fmaxf(s2[0], s2[1]), fmaxf(s2[2], s2[3]));
        mx = fmaxf(mx, __shfl_xor_sync(0xffffffffu, mx, 1));
        mx = fmaxf(mx, __shfl_xor_sync(0xffffffffu, mx, 2));
        mx = fmaxf(mx, __shfl_xor_sync(0xffffffffu, mx, 4));
        float m2n = fmaxf(m2, mx);
        float sc2 = __expf(m2 - m2n);
        float rs2 = 0.f;
        #pragma unroll
        for (int j = 0; j < 4; j++) {
            float p = __expf(s2[j] - m2n);
            rs2 += p;
            Ps2[r * 33 + cg + (j << 3)] = p;
        }
        rs2 += __shfl_xor_sync(0xffffffffu, rs2, 1);
        rs2 += __shfl_xor_sync(0xffffffffu, rs2, 2);
        rs2 += __shfl_xor_sync(0xffffffffu, rs2, 4);
        l2 = l2 * sc2 + rs2;  m2 = m2n;

        __syncwarp();   // P rows are produced/consumed within one warp

        // ---- P·V accumulation (shared V tile for both accumulators) ----
        #pragma unroll
        for (int i = 0; i < 16; i++) { O1[i] *= sc1; O2[i] *= sc2; }
        #pragma unroll 8
        for (int k = 0; k < 32; k++) {
            float p1 = Ps1[r * 33 + k];
            float p2 = Ps2[r * 33 + k];
            #pragma unroll
            for (int i = 0; i < 16; i++) {
                float v = Vs[k * 128 + cg + (i << 3)];
                O1[i] += p1 * v;
                O2[i] += p2 * v;
            }
        }
    }

    // ---- epilogue: combine heads, RMSNorm over 128 dims, gain, scale ----
    const float lam = g_lam;
    const float i1 = 1.f / l1;
    const float i2 = lam / l2;
    float o[16], ss = 0.f;
    #pragma unroll
    for (int i = 0; i < 16; i++) {
        o[i] = O1[i] * i1 - O2[i] * i2;
        ss += o[i] * o[i];
    }
    ss += __shfl_xor_sync(0xffffffffu, ss, 1);
    ss += __shfl_xor_sync(0xffffffffu, ss, 2);
    ss += __shfl_xor_sync(0xffffffffu, ss, 4);
    const float rms  = rsqrtf(ss * (1.0f / 128.f) + 1e-5f);
    const float post = (1.f - LAMBDA_INIT_F) * rms;
    #pragma unroll
    for (int i = 0; i < 16; i++) {
        int c = cg + (i << 3);
        g_A[(size_t)(qb + r) * EMB + cv + c] = o[i] * post * gw[c];
    }
}

// ---------------------------------------------------------------------------
// kernel_launch
// ---------------------------------------------------------------------------
extern "C" void kernel_launch(void* const* d_in, const int* in_sizes, int n_in,
                              void* d_out, int out_size)
{
    const float* query = (const float*)d_in[0];
    const float* key_  = (const float*)d_in[1];
    const float* value = (const float*)d_in[2];
    // d_in[3] rel_pos, d_in[4] attn_mask — both no-ops here
    const float* Wq = (const float*)d_in[5];
    const float* Wk = (const float*)d_in[6];
    const float* Wv = (const float*)d_in[7];
    const float* Wo = (const float*)d_in[8];
    const float* lq1 = (const float*)d_in[9];
    const float* lk1 = (const float*)d_in[10];
    const float* lq2 = (const float*)d_in[11];
    const float* lk2 = (const float*)d_in[12];
    const float* gw  = (const float*)d_in[13];
    float* out = (float*)d_out;

    float *pQ, *pK, *pV, *pA;
    cudaGetSymbolAddress((void**)&pQ, g_Q);
    cudaGetSymbolAddress((void**)&pK, g_K);
    cudaGetSymbolAddress((void**)&pV, g_V);
    cudaGetSymbolAddress((void**)&pA, g_A);

    cudaFuncSetAttribute(diffattn_kernel,
                         cudaFuncAttributeMaxDynamicSharedMemorySize, ATT_SMEM_BYTES);

    lam_kernel<<<1, 32>>>(lq1, lk1, lq2, lk2);

    dim3 ggrid(SQ / 128, SQ / 128);
    gemm_nt<<<ggrid, 256>>>(query, Wq, pQ);
    gemm_nt<<<ggrid, 256>>>(key_,  Wk, pK);
    gemm_nt<<<ggrid, 256>>>(value, Wv, pV);

    dim3 agrid(SQ / 32, NH);
    diffattn_kernel<<<agrid, 256, ATT_SMEM_BYTES>>>(gw);

    gemm_nt<<<ggrid, 256>>>(pA, Wo, out);
}

// round 6
// speedup vs baseline: 1.1072x; 1.1072x over previous
#include <cuda_runtime.h>
#include <cuda_bf16.h>
#include <math.h>

// Problem constants
#define SQ   2048          // sequence length (= M = N = K of all GEMMs)
#define EMB  2048
#define NH   16            // output heads
#define HD   64            // differential head dim
#define VD   128           // value head dim = 2*HD

// 0.8 - 0.6*exp(-0.3*12) as a compile-time literal (usable in device code)
#define LAMBDA_INIT_F 0.7836057665316245f

// ---------------------------------------------------------------------------
// Scratch (static __device__ allocations only — no cudaMalloc allowed)
// ---------------------------------------------------------------------------
__device__ float g_Q[SQ * EMB];
__device__ float g_K[SQ * EMB];
__device__ float g_V[SQ * EMB];
__device__ float g_A[SQ * EMB];   // post-attention, post-RMSNorm activations
__device__ float g_lam;           // lambda_full

// ---------------------------------------------------------------------------
// lambda_full = exp(sum lq1*lk1) - exp(sum lq2*lk2) + LAMBDA_INIT
// ---------------------------------------------------------------------------
__global__ void lam_kernel(const float* __restrict__ lq1, const float* __restrict__ lk1,
                           const float* __restrict__ lq2, const float* __restrict__ lk2)
{
    int t = threadIdx.x;   // 32 threads
    float a = lq1[t] * lk1[t] + lq1[t + 32] * lk1[t + 32];
    float b = lq2[t] * lk2[t] + lq2[t + 32] * lk2[t + 32];
    #pragma unroll
    for (int o = 16; o; o >>= 1) {
        a += __shfl_xor_sync(0xffffffffu, a, o);
        b += __shfl_xor_sync(0xffffffffu, b, o);
    }
    if (t == 0) g_lam = expf(a) - expf(b) + LAMBDA_INIT_F;
}

// ---------------------------------------------------------------------------
// tf32 helpers
// ---------------------------------------------------------------------------
__device__ __forceinline__ unsigned f2tf(float x) {
    unsigned r;
    asm("cvt.rna.tf32.f32 %0, %1;" : "=r"(r) : "f"(x));
    return r;
}

__device__ __forceinline__ void mma_tf32(float* d, const unsigned* a, const unsigned* b) {
    asm volatile(
        "mma.sync.aligned.m16n8k8.row.col.f32.tf32.tf32.f32 "
        "{%0,%1,%2,%3}, {%4,%5,%6,%7}, {%8,%9}, {%0,%1,%2,%3};"
        : "+f"(d[0]), "+f"(d[1]), "+f"(d[2]), "+f"(d[3])
        : "r"(a[0]), "r"(a[1]), "r"(a[2]), "r"(a[3]), "r"(b[0]), "r"(b[1]));
}

// Split x into tf32 hi + tf32 lo such that hi+lo ~= x to ~2^-22.
__device__ __forceinline__ void tf_split(float x, unsigned& hi, unsigned& lo) {
    hi = f2tf(x);
    lo = f2tf(x - __uint_as_float(hi));
}

// ---------------------------------------------------------------------------
// 3xTF32 GEMM:  C[i,j] = sum_k A[i,k] * B[j,k]   (A: MxK row-major, B: NxK row-major)
// All dims = 2048.  128x128 block tile, BK=32, 256 threads (8 warps = 2x4),
// warp tile 64x32, mma.sync m16n8k8 tf32 with hi/lo error-compensated split.
// ---------------------------------------------------------------------------
__global__ __launch_bounds__(256, 2) void gemm_tf32(const float* __restrict__ A,
                                                    const float* __restrict__ B,
                                                    float* __restrict__ C)
{
    __shared__ float As[128][36];   // [row within tile][k within BK], pad->conflict-free
    __shared__ float Bs[128][36];

    const int tid    = threadIdx.x;
    const int wid    = tid >> 5;
    const int lane   = tid & 31;
    const int warp_m = wid >> 2;            // 0..1  -> 64-row slab
    const int warp_n = wid & 3;             // 0..3  -> 32-col slab
    const int grp    = lane >> 2;           // 0..7
    const int t4     = lane & 3;            // 0..3
    const int bm     = blockIdx.y << 7;
    const int bn     = blockIdx.x << 7;

    float acc[4][4][4];                     // [mt][nt][frag]
    #pragma unroll
    for (int i = 0; i < 4; i++)
        #pragma unroll
        for (int j = 0; j < 4; j++)
            #pragma unroll
            for (int q = 0; q < 4; q++) acc[i][j][q] = 0.f;

    for (int k0 = 0; k0 < SQ; k0 += 32) {
        // ---- load 128x32 A and B tiles (each thread: 4 float4 per matrix) ----
        #pragma unroll
        for (int i = 0; i < 4; i++) {
            int idx = tid + (i << 8);
            int row = idx >> 3;
            int c   = (idx & 7) << 2;
            *(float4*)&As[row][c] = *(const float4*)(A + (size_t)(bm + row) * SQ + k0 + c);
            *(float4*)&Bs[row][c] = *(const float4*)(B + (size_t)(bn + row) * SQ + k0 + c);
        }
        __syncthreads();

        #pragma unroll
        for (int kc = 0; kc < 4; kc++) {
            const int kb = kc << 3;

            // B fragments for all 4 n-tiles (col-major k8 x n8: b0=(k=t4,n=grp), b1=(k=t4+4))
            unsigned bh[4][2], bl[4][2];
            #pragma unroll
            for (int nt = 0; nt < 4; nt++) {
                int col = (warp_n << 5) + (nt << 3) + grp;
                tf_split(Bs[col][kb + t4],     bh[nt][0], bl[nt][0]);
                tf_split(Bs[col][kb + t4 + 4], bh[nt][1], bl[nt][1]);
            }

            #pragma unroll
            for (int mt = 0; mt < 4; mt++) {
                int rbase = (warp_m << 6) + (mt << 4);
                unsigned ah[4], al[4];
                tf_split(As[rbase + grp][kb + t4],         ah[0], al[0]);
                tf_split(As[rbase + grp + 8][kb + t4],     ah[1], al[1]);
                tf_split(As[rbase + grp][kb + t4 + 4],     ah[2], al[2]);
                tf_split(As[rbase + grp + 8][kb + t4 + 4], ah[3], al[3]);

                #pragma unroll
                for (int nt = 0; nt < 4; nt++) {
                    mma_tf32(acc[mt][nt], ah, bh[nt]);   // hi*hi
                    mma_tf32(acc[mt][nt], ah, bl[nt]);   // hi*lo
                    mma_tf32(acc[mt][nt], al, bh[nt]);   // lo*hi
                }
            }
        }
        __syncthreads();
    }

    // ---- store: c0/c1 at (row, 2*t4 / +1), c2/c3 at (row+8, ...) ----
    #pragma unroll
    for (int mt = 0; mt < 4; mt++) {
        int row0 = bm + (warp_m << 6) + (mt << 4) + grp;
        #pragma unroll
        for (int nt = 0; nt < 4; nt++) {
            int col = bn + (warp_n << 5) + (nt << 3) + (t4 << 1);
            *(float2*)(C + (size_t)row0 * SQ + col)       = make_float2(acc[mt][nt][0], acc[mt][nt][1]);
            *(float2*)(C + (size_t)(row0 + 8) * SQ + col) = make_float2(acc[mt][nt][2], acc[mt][nt][3]);
        }
    }
}

// ---------------------------------------------------------------------------
// Fused differential flash-attention + RMSNorm epilogue.
// Grid: (SQ/32, NH).  Block: 256 threads.
// ---------------------------------------------------------------------------
#define ATT_SMEM_FLOATS (4*32*68 + 32*128 + 2*32*33)
#define ATT_SMEM_BYTES  (ATT_SMEM_FLOATS * 4)

__global__ __launch_bounds__(256) void diffattn_kernel(const float* __restrict__ gw)
{
    extern __shared__ float sm[];
    float* Q1s = sm;                 // [32][68]
    float* Q2s = Q1s + 32 * 68;
    float* K1s = Q2s + 32 * 68;
    float* K2s = K1s + 32 * 68;
    float* Vs  = K2s + 32 * 68;      // [32][128]
    float* Ps1 = Vs  + 32 * 128;     // [32][33]
    float* Ps2 = Ps1 + 32 * 33;

    const int h  = blockIdx.y;
    const int qb = blockIdx.x << 5;
    const int c1 = h << 7;           // score head 2h   -> cols [128h, 128h+64)
    const int c2 = c1 + 64;         // score head 2h+1 -> cols [128h+64, 128h+128)
    const int cv = h << 7;           // value head h    -> cols [128h, 128h+128)

    const int tid = threadIdx.x;
    const int r   = tid >> 3;        // query row within tile (0..31)
    const int cg  = tid & 7;         // column group (0..7)

    // Load Q tiles (scaled by HD^-0.5)
    const float qscale = 0.125f;
    #pragma unroll
    for (int i = 0; i < 2; i++) {
        int idx = tid + (i << 8);
        int row = idx >> 4, c = (idx & 15) << 2;
        float4 a = *(const float4*)&g_Q[(size_t)(qb + row) * EMB + c1 + c];
        float4 b = *(const float4*)&g_Q[(size_t)(qb + row) * EMB + c2 + c];
        *(float4*)&Q1s[row * 68 + c] = make_float4(a.x*qscale, a.y*qscale, a.z*qscale, a.w*qscale);
        *(float4*)&Q2s[row * 68 + c] = make_float4(b.x*qscale, b.y*qscale, b.z*qscale, b.w*qscale);
    }

    float O1[16], O2[16];
    #pragma unroll
    for (int i = 0; i < 16; i++) { O1[i] = 0.f; O2[i] = 0.f; }
    float m1 = -1e30f, l1 = 0.f, m2 = -1e30f, l2 = 0.f;

    for (int kb = 0; kb < SQ; kb += 32) {
        __syncthreads();   // previous tile's compute done before overwrite
        #pragma unroll
        for (int i = 0; i < 2; i++) {
            int idx = tid + (i << 8);
            int row = idx >> 4, c = (idx & 15) << 2;
            *(float4*)&K1s[row * 68 + c] = *(const float4*)&g_K[(size_t)(kb + row) * EMB + c1 + c];
            *(float4*)&K2s[row * 68 + c] = *(const float4*)&g_K[(size_t)(kb + row) * EMB + c2 + c];
        }
        #pragma unroll
        for (int i = 0; i < 4; i++) {
            int idx = tid + (i << 8);
            int row = idx >> 5, c = (idx & 31) << 2;
            *(float4*)&Vs[row * 128 + c] = *(const float4*)&g_V[(size_t)(kb + row) * EMB + cv + c];
        }
        __syncthreads();

        // ---- scores: S1/S2 [32x32] for both score heads ----
        float s1[4] = {0.f,0.f,0.f,0.f}, s2[4] = {0.f,0.f,0.f,0.f};
        #pragma unroll 4
        for (int d = 0; d < 64; d += 4) {
            float4 q1 = *(const float4*)&Q1s[r * 68 + d];
            float4 q2 = *(const float4*)&Q2s[r * 68 + d];
            #pragma unroll
            for (int j = 0; j < 4; j++) {
                int c = cg + (j << 3);
                float4 k1 = *(const float4*)&K1s[c * 68 + d];
                float4 k2 = *(const float4*)&K2s[c * 68 + d];
                s1[j] += q1.x*k1.x + q1.y*k1.y + q1.z*k1.z + q1.w*k1.w;
                s2[j] += q2.x*k2.x + q2.y*k2.y + q2.z*k2.z + q2.w*k2.w;
            }
        }

        // ---- online softmax, head 1 ----
        float mx = fmaxf(fmaxf(s1[0], s1[1]), fmaxf(s1[2], s1[3]));
        mx = fmaxf(mx, __shfl_xor_sync(0xffffffffu, mx, 1));
        mx = fmaxf(mx, __shfl_xor_sync(0xffffffffu, mx, 2));
        mx = fmaxf(mx, __shfl_xor_sync(0xffffffffu, mx, 4));
        float m1n = fmaxf(m1, mx);
        float sc1 = __expf(m1 - m1n);
        float rs1 = 0.f;
        #pragma unroll
        for (int j = 0; j < 4; j++) {
            float p = __expf(s1[j] - m1n);
            rs1 += p;
            Ps1[r * 33 + cg + (j << 3)] = p;
        }
        rs1 += __shfl_xor_sync(0xffffffffu, rs1, 1);
        rs1 += __shfl_xor_sync(0xffffffffu, rs1, 2);
        rs1 += __shfl_xor_sync(0xffffffffu, rs1, 4);
        l1 = l1 * sc1 + rs1;  m1 = m1n;

        // ---- online softmax, head 2 ----
        mx = fmaxf(fmaxf(s2[0], s2[1]), fmaxf(s2[2], s2[3]));
        mx = fmaxf(mx, __shfl_xor_sync(0xffffffffu, mx, 1));
        mx = fmaxf(mx, __shfl_xor_sync(0xffffffffu, mx, 2));
        mx = fmaxf(mx, __shfl_xor_sync(0xffffffffu, mx, 4));
        float m2n = fmaxf(m2, mx);
        float sc2 = __expf(m2 - m2n);
        float rs2 = 0.f;
        #pragma unroll
        for (int j = 0; j < 4; j++) {
            float p = __expf(s2[j] - m2n);
            rs2 += p;
            Ps2[r * 33 + cg + (j << 3)] = p;
        }
        rs2 += __shfl_xor_sync(0xffffffffu, rs2, 1);
        rs2 += __shfl_xor_sync(0xffffffffu, rs2, 2);
        rs2 += __shfl_xor_sync(0xffffffffu, rs2, 4);
        l2 = l2 * sc2 + rs2;  m2 = m2n;

        __syncwarp();   // P rows are produced/consumed within one warp

        // ---- P·V accumulation (shared V tile for both accumulators) ----
        #pragma unroll
        for (int i = 0; i < 16; i++) { O1[i] *= sc1; O2[i] *= sc2; }
        #pragma unroll 8
        for (int k = 0; k < 32; k++) {
            float p1 = Ps1[r * 33 + k];
            float p2 = Ps2[r * 33 + k];
            #pragma unroll
            for (int i = 0; i < 16; i++) {
                float v = Vs[k * 128 + cg + (i << 3)];
                O1[i] += p1 * v;
                O2[i] += p2 * v;
            }
        }
    }

    // ---- epilogue: combine heads, RMSNorm over 128 dims, gain, scale ----
    const float lam = g_lam;
    const float i1 = 1.f / l1;
    const float i2 = lam / l2;
    float o[16], ss = 0.f;
    #pragma unroll
    for (int i = 0; i < 16; i++) {
        o[i] = O1[i] * i1 - O2[i] * i2;
        ss += o[i] * o[i];
    }
    ss += __shfl_xor_sync(0xffffffffu, ss, 1);
    ss += __shfl_xor_sync(0xffffffffu, ss, 2);
    ss += __shfl_xor_sync(0xffffffffu, ss, 4);
    const float rms  = rsqrtf(ss * (1.0f / 128.f) + 1e-5f);
    const float post = (1.f - LAMBDA_INIT_F) * rms;
    #pragma unroll
    for (int i = 0; i < 16; i++) {
        int c = cg + (i << 3);
        g_A[(size_t)(qb + r) * EMB + cv + c] = o[i] * post * gw[c];
    }
}

// ---------------------------------------------------------------------------
// kernel_launch
// ---------------------------------------------------------------------------
extern "C" void kernel_launch(void* const* d_in, const int* in_sizes, int n_in,
                              void* d_out, int out_size)
{
    const float* query = (const float*)d_in[0];
    const float* key_  = (const float*)d_in[1];
    const float* value = (const float*)d_in[2];
    // d_in[3] rel_pos, d_in[4] attn_mask — both no-ops here
    const float* Wq = (const float*)d_in[5];
    const float* Wk = (const float*)d_in[6];
    const float* Wv = (const float*)d_in[7];
    const float* Wo = (const float*)d_in[8];
    const float* lq1 = (const float*)d_in[9];
    const float* lk1 = (const float*)d_in[10];
    const float* lq2 = (const float*)d_in[11];
    const float* lk2 = (const float*)d_in[12];
    const float* gw  = (const float*)d_in[13];
    float* out = (float*)d_out;

    float *pQ, *pK, *pV, *pA;
    cudaGetSymbolAddress((void**)&pQ, g_Q);
    cudaGetSymbolAddress((void**)&pK, g_K);
    cudaGetSymbolAddress((void**)&pV, g_V);
    cudaGetSymbolAddress((void**)&pA, g_A);

    cudaFuncSetAttribute(diffattn_kernel,
                         cudaFuncAttributeMaxDynamicSharedMemorySize, ATT_SMEM_BYTES);

    lam_kernel<<<1, 32>>>(lq1, lk1, lq2, lk2);

    dim3 ggrid(SQ / 128, SQ / 128);
    gemm_tf32<<<ggrid, 256>>>(query, Wq, pQ);
    gemm_tf32<<<ggrid, 256>>>(key_,  Wk, pK);
    gemm_tf32<<<ggrid, 256>>>(value, Wv, pV);

    dim3 agrid(SQ / 32, NH);
    diffattn_kernel<<<agrid, 256, ATT_SMEM_BYTES>>>(gw);

    gemm_tf32<<<ggrid, 256>>>(pA, Wo, out);
}

// round 8
// speedup vs baseline: 1.9754x; 1.7840x over previous
#include <cuda_runtime.h>
#include <cuda_bf16.h>
#include <math.h>

// Problem constants
#define SQ   2048          // sequence length (= M = N = K of all GEMMs)
#define EMB  2048
#define NH   16            // output heads
#define HD   64            // differential head dim
#define VD   128           // value head dim = 2*HD

// 0.8 - 0.6*exp(-0.3*12) as a compile-time literal (usable in device code)
#define LAMBDA_INIT_F 0.7836057665316245f

// ---------------------------------------------------------------------------
// Scratch (static __device__ allocations only — no cudaMalloc allowed)
// ---------------------------------------------------------------------------
__device__ float g_Q[SQ * EMB];
__device__ float g_K[SQ * EMB];
__device__ float g_V[SQ * EMB];
__device__ float g_A[SQ * EMB];   // post-attention, post-RMSNorm activations
__device__ float g_lam;           // lambda_full

// ---------------------------------------------------------------------------
// lambda_full = exp(sum lq1*lk1) - exp(sum lq2*lk2) + LAMBDA_INIT
// ---------------------------------------------------------------------------
__global__ void lam_kernel(const float* __restrict__ lq1, const float* __restrict__ lk1,
                           const float* __restrict__ lq2, const float* __restrict__ lk2)
{
    int t = threadIdx.x;   // 32 threads
    float a = lq1[t] * lk1[t] + lq1[t + 32] * lk1[t + 32];
    float b = lq2[t] * lk2[t] + lq2[t + 32] * lk2[t + 32];
    #pragma unroll
    for (int o = 16; o; o >>= 1) {
        a += __shfl_xor_sync(0xffffffffu, a, o);
        b += __shfl_xor_sync(0xffffffffu, b, o);
    }
    if (t == 0) g_lam = expf(a) - expf(b) + LAMBDA_INIT_F;
}

// ---------------------------------------------------------------------------
// tf32 helpers
// ---------------------------------------------------------------------------
__device__ __forceinline__ unsigned f2tf(float x) {
    unsigned r;
    asm("cvt.rna.tf32.f32 %0, %1;" : "=r"(r) : "f"(x));
    return r;
}

__device__ __forceinline__ void mma_tf32(float* d, const unsigned* a, const unsigned* b) {
    asm volatile(
        "mma.sync.aligned.m16n8k8.row.col.f32.tf32.tf32.f32 "
        "{%0,%1,%2,%3}, {%4,%5,%6,%7}, {%8,%9}, {%0,%1,%2,%3};"
        : "+f"(d[0]), "+f"(d[1]), "+f"(d[2]), "+f"(d[3])
        : "r"(a[0]), "r"(a[1]), "r"(a[2]), "r"(a[3]), "r"(b[0]), "r"(b[1]));
}

// Split x into tf32 hi + tf32 lo such that hi+lo ~= x to ~2^-22.
__device__ __forceinline__ void tf_split(float x, unsigned& hi, unsigned& lo) {
    hi = f2tf(x);
    lo = f2tf(x - __uint_as_float(hi));
}

// ---------------------------------------------------------------------------
// 3xTF32 GEMM with pre-split hi/lo smem planes.
// C[i,j] = sum_k A[i,k]*B[j,k].  128x128 tile, BK=32, 256 thr, warp tile 64x32.
// ---------------------------------------------------------------------------
#define GEMM_SMEM_BYTES (4 * 128 * 36 * 4)

__global__ __launch_bounds__(256, 2) void gemm_tf32(const float* __restrict__ A,
                                                    const float* __restrict__ B,
                                                    float* __restrict__ C)
{
    extern __shared__ float gsm[];
    float* Ah = gsm;                 // [128][36]
    float* Al = Ah + 128 * 36;
    float* Bh = Al + 128 * 36;
    float* Bl = Bh + 128 * 36;

    const int tid    = threadIdx.x;
    const int wid    = tid >> 5;
    const int lane   = tid & 31;
    const int warp_m = wid >> 2;            // 0..1  -> 64-row slab
    const int warp_n = wid & 3;             // 0..3  -> 32-col slab
    const int grp    = lane >> 2;           // 0..7
    const int t4     = lane & 3;            // 0..3
    const int bm     = blockIdx.y << 7;
    const int bn     = blockIdx.x << 7;

    float acc[4][4][4];
    #pragma unroll
    for (int i = 0; i < 4; i++)
        #pragma unroll
        for (int j = 0; j < 4; j++)
            #pragma unroll
            for (int q = 0; q < 4; q++) acc[i][j][q] = 0.f;

    for (int k0 = 0; k0 < SQ; k0 += 32) {
        #pragma unroll
        for (int i = 0; i < 4; i++) {
            int idx = tid + (i << 8);
            int row = idx >> 3;
            int c   = (idx & 7) << 2;
            unsigned h0,l0,h1,l1,h2,l2,h3,l3;
            float4 va = *(const float4*)(A + (size_t)(bm + row) * SQ + k0 + c);
            tf_split(va.x,h0,l0); tf_split(va.y,h1,l1);
            tf_split(va.z,h2,l2); tf_split(va.w,h3,l3);
            *(float4*)&Ah[row*36+c] = make_float4(__uint_as_float(h0),__uint_as_float(h1),
                                                  __uint_as_float(h2),__uint_as_float(h3));
            *(float4*)&Al[row*36+c] = make_float4(__uint_as_float(l0),__uint_as_float(l1),
                                                  __uint_as_float(l2),__uint_as_float(l3));
            float4 vb = *(const float4*)(B + (size_t)(bn + row) * SQ + k0 + c);
            tf_split(vb.x,h0,l0); tf_split(vb.y,h1,l1);
            tf_split(vb.z,h2,l2); tf_split(vb.w,h3,l3);
            *(float4*)&Bh[row*36+c] = make_float4(__uint_as_float(h0),__uint_as_float(h1),
                                                  __uint_as_float(h2),__uint_as_float(h3));
            *(float4*)&Bl[row*36+c] = make_float4(__uint_as_float(l0),__uint_as_float(l1),
                                                  __uint_as_float(l2),__uint_as_float(l3));
        }
        __syncthreads();

        #pragma unroll
        for (int kc = 0; kc < 4; kc++) {
            const int kb = kc << 3;
            unsigned bh[4][2], bl[4][2];
            #pragma unroll
            for (int nt = 0; nt < 4; nt++) {
                int col = (warp_n << 5) + (nt << 3) + grp;
                bh[nt][0] = __float_as_uint(Bh[col*36 + kb + t4]);
                bh[nt][1] = __float_as_uint(Bh[col*36 + kb + t4 + 4]);
                bl[nt][0] = __float_as_uint(Bl[col*36 + kb + t4]);
                bl[nt][1] = __float_as_uint(Bl[col*36 + kb + t4 + 4]);
            }
            #pragma unroll
            for (int mt = 0; mt < 4; mt++) {
                int rbase = (warp_m << 6) + (mt << 4);
                unsigned ah[4], al[4];
                ah[0] = __float_as_uint(Ah[(rbase+grp)*36   + kb + t4]);
                ah[1] = __float_as_uint(Ah[(rbase+grp+8)*36 + kb + t4]);
                ah[2] = __float_as_uint(Ah[(rbase+grp)*36   + kb + t4 + 4]);
                ah[3] = __float_as_uint(Ah[(rbase+grp+8)*36 + kb + t4 + 4]);
                al[0] = __float_as_uint(Al[(rbase+grp)*36   + kb + t4]);
                al[1] = __float_as_uint(Al[(rbase+grp+8)*36 + kb + t4]);
                al[2] = __float_as_uint(Al[(rbase+grp)*36   + kb + t4 + 4]);
                al[3] = __float_as_uint(Al[(rbase+grp+8)*36 + kb + t4 + 4]);
                #pragma unroll
                for (int nt = 0; nt < 4; nt++) {
                    mma_tf32(acc[mt][nt], ah, bh[nt]);
                    mma_tf32(acc[mt][nt], ah, bl[nt]);
                    mma_tf32(acc[mt][nt], al, bh[nt]);
                }
            }
        }
        __syncthreads();
    }

    #pragma unroll
    for (int mt = 0; mt < 4; mt++) {
        int row0 = bm + (warp_m << 6) + (mt << 4) + grp;
        #pragma unroll
        for (int nt = 0; nt < 4; nt++) {
            int col = bn + (warp_n << 5) + (nt << 3) + (t4 << 1);
            *(float2*)(C + (size_t)row0 * SQ + col)       = make_float2(acc[mt][nt][0], acc[mt][nt][1]);
            *(float2*)(C + (size_t)(row0 + 8) * SQ + col) = make_float2(acc[mt][nt][2], acc[mt][nt][3]);
        }
    }
}

// ---------------------------------------------------------------------------
// Tensor-core differential flash-attention + fused RMSNorm.
// Grid (SQ/64, NH), 256 threads (8 warps).
// Warp w = (slab = w>>1 in 0..3 -> rows slab*16.., sel = w&1).
//  S-phase : warp computes S for (16 rows x 64 keys) of score head `sel`
//            via 3xTF32 mma, softmax in-warp, P (tf32) + sc -> smem.
//  PV-phase: warp accumulates O for (16 rows x V-half `sel` x BOTH heads)
//            via single tf32 mma, A-frags from P smem, B-frags from Vt smem.
// ---------------------------------------------------------------------------
#define ATT_SMEM_FLOATS (2*64*68 + 2*64*68 + 128*68 + 2*64*68 + 128 + 128 + 64)
#define ATT_SMEM_BYTES  (ATT_SMEM_FLOATS * 4)

__global__ __launch_bounds__(256) void diffattn_tc(const float* __restrict__ gw)
{
    extern __shared__ float sm[];
    float* Qs  = sm;                  // [2][64][68]  scaled Q, raw fp32
    float* Ks  = Qs  + 2*64*68;       // [2][64][68]  raw fp32
    float* Vt  = Ks  + 2*64*68;       // [128][68]    transposed, tf32-rounded
    float* Ps  = Vt  + 128*68;        // [2][64][68]  probs, tf32-rounded
    float* scs = Ps  + 2*64*68;       // [2][64]      per-tile rescale factors
    float* ls  = scs + 128;           // [2][64]      final softmax denominators
    float* rss = ls  + 128;           // [64]         row sum-of-squares

    const int h   = blockIdx.y;
    const int qb  = blockIdx.x << 6;      // 64 query rows
    const int c1  = h << 7;               // Q/K cols: head1 at +0, head2 at +64
    const int cv  = h << 7;               // V cols

    const int tid  = threadIdx.x;
    const int wid  = tid >> 5;
    const int lane = tid & 31;
    const int grp  = lane >> 2;           // 0..7
    const int t4   = lane & 3;            // 0..3
    const int slab = wid >> 1;            // 0..3 : rows slab*16 .. +15
    const int sel  = wid & 1;             // S-phase head / PV-phase V-half
    const int r_lo = slab*16 + grp;       // this lane's two fragment rows
    const int r_hi = r_lo + 8;

    if (tid < 64) rss[tid] = 0.f;

    // ---- load Q (both heads), scaled by HD^-0.5 ----
    const float qscale = 0.125f;
    #pragma unroll
    for (int i = 0; i < 8; i++) {
        int idx = tid + (i << 8);         // 0..2047 float4s
        int row = idx >> 5;
        int rem = idx & 31;
        int hh  = rem >> 4;
        int c   = (rem & 15) << 2;
        float4 a = *(const float4*)&g_Q[(size_t)(qb + row) * EMB + c1 + (hh << 6) + c];
        *(float4*)&Qs[(hh*64 + row)*68 + c] =
            make_float4(a.x*qscale, a.y*qscale, a.z*qscale, a.w*qscale);
    }

    const float* Qh = Qs + sel*64*68;
    const float* Kh = Ks + sel*64*68;
    float*       Ph = Ps + sel*64*68;

    float O[2][8][4];                     // [head][nt][frag], V cols sel*64 + nt*8 + 2*t4
    #pragma unroll
    for (int hh = 0; hh < 2; hh++)
        #pragma unroll
        for (int nt = 0; nt < 8; nt++)
            #pragma unroll
            for (int q = 0; q < 4; q++) O[hh][nt][q] = 0.f;

    float m_lo = -1e30f, m_hi = -1e30f, l_lo = 0.f, l_hi = 0.f;

    for (int kb = 0; kb < SQ; kb += 64) {
        __syncthreads();                  // prev PV done before overwriting K/Vt
        // ---- load K tiles (both heads) ----
        #pragma unroll
        for (int i = 0; i < 8; i++) {
            int idx = tid + (i << 8);
            int row = idx >> 5;
            int rem = idx & 31;
            int hh  = rem >> 4;
            int c   = (rem & 15) << 2;
            *(float4*)&Ks[(hh*64 + row)*68 + c] =
                *(const float4*)&g_K[(size_t)(kb + row) * EMB + c1 + (hh << 6) + c];
        }
        // ---- load V transposed + tf32-round ----
        #pragma unroll
        for (int i = 0; i < 8; i++) {
            int idx = tid + (i << 8);
            int row = idx & 63;
            int dg  = idx >> 6;           // 0..31
            float4 v = *(const float4*)&g_V[(size_t)(kb + row) * EMB + cv + (dg << 2)];
            Vt[(dg*4+0)*68 + row] = __uint_as_float(f2tf(v.x));
            Vt[(dg*4+1)*68 + row] = __uint_as_float(f2tf(v.y));
            Vt[(dg*4+2)*68 + row] = __uint_as_float(f2tf(v.z));
            Vt[(dg*4+3)*68 + row] = __uint_as_float(f2tf(v.w));
        }
        __syncthreads();

        // ---- S = Q_sel K_sel^T  (16 rows x 64 keys), 3xTF32 ----
        float sacc[8][4];
        #pragma unroll
        for (int nt = 0; nt < 8; nt++)
            #pragma unroll
            for (int q = 0; q < 4; q++) sacc[nt][q] = 0.f;

        #pragma unroll
        for (int ks = 0; ks < 8; ks++) {
            const int kc = ks << 3;
            unsigned ah[4], al[4];
            tf_split(Qh[r_lo*68 + kc + t4],     ah[0], al[0]);
            tf_split(Qh[r_hi*68 + kc + t4],     ah[1], al[1]);
            tf_split(Qh[r_lo*68 + kc + t4 + 4], ah[2], al[2]);
            tf_split(Qh[r_hi*68 + kc + t4 + 4], ah[3], al[3]);
            #pragma unroll
            for (int nt = 0; nt < 8; nt++) {
                unsigned bh[2], bl[2];
                tf_split(Kh[(nt*8+grp)*68 + kc + t4],     bh[0], bl[0]);
                tf_split(Kh[(nt*8+grp)*68 + kc + t4 + 4], bh[1], bl[1]);
                mma_tf32(sacc[nt], ah, bh);
                mma_tf32(sacc[nt], ah, bl);
                mma_tf32(sacc[nt], al, bh);
            }
        }

        // ---- online softmax (rows r_lo via c0/c1, r_hi via c2/c3) ----
        float mx_lo = -1e30f, mx_hi = -1e30f;
        #pragma unroll
        for (int nt = 0; nt < 8; nt++) {
            mx_lo = fmaxf(mx_lo, fmaxf(sacc[nt][0], sacc[nt][1]));
            mx_hi = fmaxf(mx_hi, fmaxf(sacc[nt][2], sacc[nt][3]));
        }
        mx_lo = fmaxf(mx_lo, __shfl_xor_sync(0xffffffffu, mx_lo, 1));
        mx_lo = fmaxf(mx_lo, __shfl_xor_sync(0xffffffffu, mx_lo, 2));
        mx_hi = fmaxf(mx_hi, __shfl_xor_sync(0xffffffffu, mx_hi, 1));
        mx_hi = fmaxf(mx_hi, __shfl_xor_sync(0xffffffffu, mx_hi, 2));
        const float mn_lo = fmaxf(m_lo, mx_lo);
        const float mn_hi = fmaxf(m_hi, mx_hi);
        const float sc_lo = __expf(m_lo - mn_lo);
        const float sc_hi = __expf(m_hi - mn_hi);
        float rs_lo = 0.f, rs_hi = 0.f;
        #pragma unroll
        for (int nt = 0; nt < 8; nt++) {
            float p0 = __expf(sacc[nt][0] - mn_lo);
            float p1 = __expf(sacc[nt][1] - mn_lo);
            float p2 = __expf(sacc[nt][2] - mn_hi);
            float p3 = __expf(sacc[nt][3] - mn_hi);
            rs_lo += p0 + p1;
            rs_hi += p2 + p3;
            int col = nt*8 + (t4 << 1);
            *(float2*)&Ph[r_lo*68 + col] =
                make_float2(__uint_as_float(f2tf(p0)), __uint_as_float(f2tf(p1)));
            *(float2*)&Ph[r_hi*68 + col] =
                make_float2(__uint_as_float(f2tf(p2)), __uint_as_float(f2tf(p3)));
        }
        rs_lo += __shfl_xor_sync(0xffffffffu, rs_lo, 1);
        rs_lo += __shfl_xor_sync(0xffffffffu, rs_lo, 2);
        rs_hi += __shfl_xor_sync(0xffffffffu, rs_hi, 1);
        rs_hi += __shfl_xor_sync(0xffffffffu, rs_hi, 2);
        l_lo = l_lo * sc_lo + rs_lo;  m_lo = mn_lo;
        l_hi = l_hi * sc_hi + rs_hi;  m_hi = mn_hi;
        if (t4 == 0) {
            scs[sel*64 + r_lo] = sc_lo;
            scs[sel*64 + r_hi] = sc_hi;
        }
        __syncthreads();

        // ---- PV: O[head] += P[head] * V  (this warp's V-half = sel) ----
        const float s1lo = scs[r_lo],      s1hi = scs[r_hi];
        const float s2lo = scs[64 + r_lo], s2hi = scs[64 + r_hi];
        #pragma unroll
        for (int hh = 0; hh < 2; hh++) {
            const float flo = hh ? s2lo : s1lo;
            const float fhi = hh ? s2hi : s1hi;
            #pragma unroll
            for (int nt = 0; nt < 8; nt++) {
                O[hh][nt][0] *= flo; O[hh][nt][1] *= flo;
                O[hh][nt][2] *= fhi; O[hh][nt][3] *= fhi;
            }
            const float* Pg = Ps + hh*64*68;
            #pragma unroll
            for (int ks = 0; ks < 8; ks++) {
                const int kc = ks << 3;
                unsigned a[4];
                a[0] = __float_as_uint(Pg[r_lo*68 + kc + t4]);
                a[1] = __float_as_uint(Pg[r_hi*68 + kc + t4]);
                a[2] = __float_as_uint(Pg[r_lo*68 + kc + t4 + 4]);
                a[3] = __float_as_uint(Pg[r_hi*68 + kc + t4 + 4]);
                #pragma unroll
                for (int nt = 0; nt < 8; nt++) {
                    unsigned b[2];
                    b[0] = __float_as_uint(Vt[(sel*64 + nt*8 + grp)*68 + kc + t4]);
                    b[1] = __float_as_uint(Vt[(sel*64 + nt*8 + grp)*68 + kc + t4 + 4]);
                    mma_tf32(O[hh][nt], a, b);
                }
            }
        }
    }

    // ---- epilogue: combine heads, RMSNorm over 128 dims, gain, scale ----
    if (t4 == 0) {
        ls[sel*64 + r_lo] = l_lo;
        ls[sel*64 + r_hi] = l_hi;
    }
    __syncthreads();
    const float lam   = g_lam;
    const float i1lo  = 1.f  / ls[r_lo],      i1hi = 1.f  / ls[r_hi];
    const float i2lo  = lam  / ls[64 + r_lo], i2hi = lam  / ls[64 + r_hi];
    float o[8][4], ss_lo = 0.f, ss_hi = 0.f;
    #pragma unroll
    for (int nt = 0; nt < 8; nt++) {
        o[nt][0] = O[0][nt][0]*i1lo - O[1][nt][0]*i2lo;
        o[nt][1] = O[0][nt][1]*i1lo - O[1][nt][1]*i2lo;
        o[nt][2] = O[0][nt][2]*i1hi - O[1][nt][2]*i2hi;
        o[nt][3] = O[0][nt][3]*i1hi - O[1][nt][3]*i2hi;
        ss_lo += o[nt][0]*o[nt][0] + o[nt][1]*o[nt][1];
        ss_hi += o[nt][2]*o[nt][2] + o[nt][3]*o[nt][3];
    }
    ss_lo += __shfl_xor_sync(0xffffffffu, ss_lo, 1);
    ss_lo += __shfl_xor_sync(0xffffffffu, ss_lo, 2);
    ss_hi += __shfl_xor_sync(0xffffffffu, ss_hi, 1);
    ss_hi += __shfl_xor_sync(0xffffffffu, ss_hi, 2);
    if (t4 == 0) {
        atomicAdd(&rss[r_lo], ss_lo);
        atomicAdd(&rss[r_hi], ss_hi);
    }
    __syncthreads();
    const float post_lo = rsqrtf(rss[r_lo] * (1.f/128.f) + 1e-5f) * (1.f - LAMBDA_INIT_F);
    const float post_hi = rsqrtf(rss[r_hi] * (1.f/128.f) + 1e-5f) * (1.f - LAMBDA_INIT_F);
    #pragma unroll
    for (int nt = 0; nt < 8; nt++) {
        int col = (sel << 6) + nt*8 + (t4 << 1);
        float g0 = gw[col], g1 = gw[col + 1];
        *(float2*)&g_A[(size_t)(qb + r_lo) * EMB + cv + col] =
            make_float2(o[nt][0]*post_lo*g0, o[nt][1]*post_lo*g1);
        *(float2*)&g_A[(size_t)(qb + r_hi) * EMB + cv + col] =
            make_float2(o[nt][2]*post_hi*g0, o[nt][3]*post_hi*g1);
    }
}

// ---------------------------------------------------------------------------
// kernel_launch
// ---------------------------------------------------------------------------
extern "C" void kernel_launch(void* const* d_in, const int* in_sizes, int n_in,
                              void* d_out, int out_size)
{
    const float* query = (const float*)d_in[0];
    const float* key_  = (const float*)d_in[1];
    const float* value = (const float*)d_in[2];
    // d_in[3] rel_pos, d_in[4] attn_mask — both no-ops here
    const float* Wq = (const float*)d_in[5];
    const float* Wk = (const float*)d_in[6];
    const float* Wv = (const float*)d_in[7];
    const float* Wo = (const float*)d_in[8];
    const float* lq1 = (const float*)d_in[9];
    const float* lk1 = (const float*)d_in[10];
    const float* lq2 = (const float*)d_in[11];
    const float* lk2 = (const float*)d_in[12];
    const float* gw  = (const float*)d_in[13];
    float* out = (float*)d_out;

    float *pQ, *pK, *pV, *pA;
    cudaGetSymbolAddress((void**)&pQ, g_Q);
    cudaGetSymbolAddress((void**)&pK, g_K);
    cudaGetSymbolAddress((void**)&pV, g_V);
    cudaGetSymbolAddress((void**)&pA, g_A);

    cudaFuncSetAttribute(gemm_tf32,
                         cudaFuncAttributeMaxDynamicSharedMemorySize, GEMM_SMEM_BYTES);
    cudaFuncSetAttribute(diffattn_tc,
                         cudaFuncAttributeMaxDynamicSharedMemorySize, ATT_SMEM_BYTES);

    lam_kernel<<<1, 32>>>(lq1, lk1, lq2, lk2);

    dim3 ggrid(SQ / 128, SQ / 128);
    gemm_tf32<<<ggrid, 256, GEMM_SMEM_BYTES>>>(query, Wq, pQ);
    gemm_tf32<<<ggrid, 256, GEMM_SMEM_BYTES>>>(key_,  Wk, pK);
    gemm_tf32<<<ggrid, 256, GEMM_SMEM_BYTES>>>(value, Wv, pV);

    dim3 agrid(SQ / 64, NH);
    diffattn_tc<<<agrid, 256, ATT_SMEM_BYTES>>>(gw);

    gemm_tf32<<<ggrid, 256, GEMM_SMEM_BYTES>>>(pA, Wo, out);
}

// round 10
// speedup vs baseline: 2.0519x; 1.0387x over previous
#include <cuda_runtime.h>
#include <cuda_bf16.h>
#include <math.h>

// Problem constants
#define SQ   2048          // sequence length (= M = N = K of all GEMMs)
#define EMB  2048
#define NH   16            // output heads
#define HD   64            // differential head dim
#define VD   128           // value head dim = 2*HD

// 0.8 - 0.6*exp(-0.3*12) as a compile-time literal (usable in device code)
#define LAMBDA_INIT_F 0.7836057665316245f

// ---------------------------------------------------------------------------
// Scratch (static __device__ allocations only — no cudaMalloc allowed)
// ---------------------------------------------------------------------------
__device__ float g_Q[SQ * EMB];
__device__ float g_K[SQ * EMB];
__device__ float g_V[SQ * EMB];
__device__ float g_A[SQ * EMB];   // post-attention, post-RMSNorm activations
__device__ float g_lam;           // lambda_full

// ---------------------------------------------------------------------------
// lambda_full = exp(sum lq1*lk1) - exp(sum lq2*lk2) + LAMBDA_INIT
// ---------------------------------------------------------------------------
__global__ void lam_kernel(const float* __restrict__ lq1, const float* __restrict__ lk1,
                           const float* __restrict__ lq2, const float* __restrict__ lk2)
{
    int t = threadIdx.x;   // 32 threads
    float a = lq1[t] * lk1[t] + lq1[t + 32] * lk1[t + 32];
    float b = lq2[t] * lk2[t] + lq2[t + 32] * lk2[t + 32];
    #pragma unroll
    for (int o = 16; o; o >>= 1) {
        a += __shfl_xor_sync(0xffffffffu, a, o);
        b += __shfl_xor_sync(0xffffffffu, b, o);
    }
    if (t == 0) g_lam = expf(a) - expf(b) + LAMBDA_INIT_F;
}

// ---------------------------------------------------------------------------
// tf32 helpers
// ---------------------------------------------------------------------------
__device__ __forceinline__ unsigned f2tf(float x) {
    unsigned r;
    asm("cvt.rna.tf32.f32 %0, %1;" : "=r"(r) : "f"(x));
    return r;
}

__device__ __forceinline__ void mma_tf32(float* d, const unsigned* a, const unsigned* b) {
    asm volatile(
        "mma.sync.aligned.m16n8k8.row.col.f32.tf32.tf32.f32 "
        "{%0,%1,%2,%3}, {%4,%5,%6,%7}, {%8,%9}, {%0,%1,%2,%3};"
        : "+f"(d[0]), "+f"(d[1]), "+f"(d[2]), "+f"(d[3])
        : "r"(a[0]), "r"(a[1]), "r"(a[2]), "r"(a[3]), "r"(b[0]), "r"(b[1]));
}

// Split x into tf32 hi + tf32 lo such that hi+lo ~= x to ~2^-22.
__device__ __forceinline__ void tf_split(float x, unsigned& hi, unsigned& lo) {
    hi = f2tf(x);
    lo = f2tf(x - __uint_as_float(hi));
}

// ---------------------------------------------------------------------------
// 3xTF32 GEMM with pre-split hi/lo smem planes.
// C[i,j] = sum_k A[i,k]*B[j,k].  128x128 tile, BK=32, 256 thr, warp tile 64x32.
// ---------------------------------------------------------------------------
#define GEMM_SMEM_BYTES (4 * 128 * 36 * 4)

__global__ __launch_bounds__(256, 2) void gemm_tf32(const float* __restrict__ A,
                                                    const float* __restrict__ B,
                                                    float* __restrict__ C)
{
    extern __shared__ float gsm[];
    float* Ah = gsm;                 // [128][36]
    float* Al = Ah + 128 * 36;
    float* Bh = Al + 128 * 36;
    float* Bl = Bh + 128 * 36;

    const int tid    = threadIdx.x;
    const int wid    = tid >> 5;
    const int lane   = tid & 31;
    const int warp_m = wid >> 2;            // 0..1  -> 64-row slab
    const int warp_n = wid & 3;             // 0..3  -> 32-col slab
    const int grp    = lane >> 2;           // 0..7
    const int t4     = lane & 3;            // 0..3
    const int bm     = blockIdx.y << 7;
    const int bn     = blockIdx.x << 7;

    float acc[4][4][4];
    #pragma unroll
    for (int i = 0; i < 4; i++)
        #pragma unroll
        for (int j = 0; j < 4; j++)
            #pragma unroll
            for (int q = 0; q < 4; q++) acc[i][j][q] = 0.f;

    for (int k0 = 0; k0 < SQ; k0 += 32) {
        #pragma unroll
        for (int i = 0; i < 4; i++) {
            int idx = tid + (i << 8);
            int row = idx >> 3;
            int c   = (idx & 7) << 2;
            unsigned h0,l0,h1,l1,h2,l2,h3,l3;
            float4 va = *(const float4*)(A + (size_t)(bm + row) * SQ + k0 + c);
            tf_split(va.x,h0,l0); tf_split(va.y,h1,l1);
            tf_split(va.z,h2,l2); tf_split(va.w,h3,l3);
            *(float4*)&Ah[row*36+c] = make_float4(__uint_as_float(h0),__uint_as_float(h1),
                                                  __uint_as_float(h2),__uint_as_float(h3));
            *(float4*)&Al[row*36+c] = make_float4(__uint_as_float(l0),__uint_as_float(l1),
                                                  __uint_as_float(l2),__uint_as_float(l3));
            float4 vb = *(const float4*)(B + (size_t)(bn + row) * SQ + k0 + c);
            tf_split(vb.x,h0,l0); tf_split(vb.y,h1,l1);
            tf_split(vb.z,h2,l2); tf_split(vb.w,h3,l3);
            *(float4*)&Bh[row*36+c] = make_float4(__uint_as_float(h0),__uint_as_float(h1),
                                                  __uint_as_float(h2),__uint_as_float(h3));
            *(float4*)&Bl[row*36+c] = make_float4(__uint_as_float(l0),__uint_as_float(l1),
                                                  __uint_as_float(l2),__uint_as_float(l3));
        }
        __syncthreads();

        #pragma unroll
        for (int kc = 0; kc < 4; kc++) {
            const int kb = kc << 3;
            unsigned bh[4][2], bl[4][2];
            #pragma unroll
            for (int nt = 0; nt < 4; nt++) {
                int col = (warp_n << 5) + (nt << 3) + grp;
                bh[nt][0] = __float_as_uint(Bh[col*36 + kb + t4]);
                bh[nt][1] = __float_as_uint(Bh[col*36 + kb + t4 + 4]);
                bl[nt][0] = __float_as_uint(Bl[col*36 + kb + t4]);
                bl[nt][1] = __float_as_uint(Bl[col*36 + kb + t4 + 4]);
            }
            #pragma unroll
            for (int mt = 0; mt < 4; mt++) {
                int rbase = (warp_m << 6) + (mt << 4);
                unsigned ah[4], al[4];
                ah[0] = __float_as_uint(Ah[(rbase+grp)*36   + kb + t4]);
                ah[1] = __float_as_uint(Ah[(rbase+grp+8)*36 + kb + t4]);
                ah[2] = __float_as_uint(Ah[(rbase+grp)*36   + kb + t4 + 4]);
                ah[3] = __float_as_uint(Ah[(rbase+grp+8)*36 + kb + t4 + 4]);
                al[0] = __float_as_uint(Al[(rbase+grp)*36   + kb + t4]);
                al[1] = __float_as_uint(Al[(rbase+grp+8)*36 + kb + t4]);
                al[2] = __float_as_uint(Al[(rbase+grp)*36   + kb + t4 + 4]);
                al[3] = __float_as_uint(Al[(rbase+grp+8)*36 + kb + t4 + 4]);
                #pragma unroll
                for (int nt = 0; nt < 4; nt++) {
                    mma_tf32(acc[mt][nt], ah, bh[nt]);
                    mma_tf32(acc[mt][nt], ah, bl[nt]);
                    mma_tf32(acc[mt][nt], al, bh[nt]);
                }
            }
        }
        __syncthreads();
    }

    #pragma unroll
    for (int mt = 0; mt < 4; mt++) {
        int row0 = bm + (warp_m << 6) + (mt << 4) + grp;
        #pragma unroll
        for (int nt = 0; nt < 4; nt++) {
            int col = bn + (warp_n << 5) + (nt << 3) + (t4 << 1);
            *(float2*)(C + (size_t)row0 * SQ + col)       = make_float2(acc[mt][nt][0], acc[mt][nt][1]);
            *(float2*)(C + (size_t)(row0 + 8) * SQ + col) = make_float2(acc[mt][nt][2], acc[mt][nt][3]);
        }
    }
}

// ---------------------------------------------------------------------------
// Tensor-core differential flash-attention + fused RMSNorm.
// Grid (SQ/64, NH), 256 threads (8 warps).
// Q is split into tf32 hi/lo smem planes ONCE before the mainloop; K is split
// at tile-load time. The S-phase inner loop is pure LDS + MMA (no cvt).
// ---------------------------------------------------------------------------
#define ATT_SMEM_FLOATS (6*64*2*68 + 128 + 128 + 64)
#define ATT_SMEM_BYTES  (ATT_SMEM_FLOATS * 4)

__global__ __launch_bounds__(256) void diffattn_tc(const float* __restrict__ gw)
{
    extern __shared__ float sm[];
    float* Qh  = sm;                  // [2][64][68]  Q hi plane (scaled)
    float* Ql  = Qh  + 2*64*68;       // [2][64][68]  Q lo plane
    float* Kh  = Ql  + 2*64*68;       // [2][64][68]  K hi plane
    float* Kl  = Kh  + 2*64*68;       // [2][64][68]  K lo plane
    float* Vt  = Kl  + 2*64*68;       // [128][68]    transposed, tf32-rounded
    float* Ps  = Vt  + 128*68;        // [2][64][68]  probs, tf32-rounded
    float* scs = Ps  + 2*64*68;       // [2][64]      per-tile rescale factors
    float* ls  = scs + 128;           // [2][64]      final softmax denominators
    float* rss = ls  + 128;           // [64]         row sum-of-squares

    const int h   = blockIdx.y;
    const int qb  = blockIdx.x << 6;      // 64 query rows
    const int c1  = h << 7;               // Q/K cols: head1 at +0, head2 at +64
    const int cv  = h << 7;               // V cols

    const int tid  = threadIdx.x;
    const int wid  = tid >> 5;
    const int lane = tid & 31;
    const int grp  = lane >> 2;           // 0..7
    const int t4   = lane & 3;            // 0..3
    const int slab = wid >> 1;            // 0..3 : rows slab*16 .. +15
    const int sel  = wid & 1;             // S-phase head / PV-phase V-half
    const int r_lo = slab*16 + grp;       // this lane's two fragment rows
    const int r_hi = r_lo + 8;

    if (tid < 64) rss[tid] = 0.f;

    // ---- load + scale + split Q (both heads) once ----
    const float qscale = 0.125f;
    #pragma unroll
    for (int i = 0; i < 8; i++) {
        int idx = tid + (i << 8);         // 0..2047 float4s
        int row = idx >> 5;
        int rem = idx & 31;
        int hh  = rem >> 4;
        int c   = (rem & 15) << 2;
        float4 a = *(const float4*)&g_Q[(size_t)(qb + row) * EMB + c1 + (hh << 6) + c];
        unsigned h0,l0,h1,l1,h2,l2,h3,l3;
        tf_split(a.x*qscale,h0,l0); tf_split(a.y*qscale,h1,l1);
        tf_split(a.z*qscale,h2,l2); tf_split(a.w*qscale,h3,l3);
        int base = (hh*64 + row)*68 + c;
        *(float4*)&Qh[base] = make_float4(__uint_as_float(h0),__uint_as_float(h1),
                                          __uint_as_float(h2),__uint_as_float(h3));
        *(float4*)&Ql[base] = make_float4(__uint_as_float(l0),__uint_as_float(l1),
                                          __uint_as_float(l2),__uint_as_float(l3));
    }

    const float* Qhh = Qh + sel*64*68;
    const float* Qll = Ql + sel*64*68;
    const float* Khh = Kh + sel*64*68;
    const float* Kll = Kl + sel*64*68;
    float*       Ph  = Ps + sel*64*68;

    float O[2][8][4];                     // [head][nt][frag], V cols sel*64 + nt*8 + 2*t4
    #pragma unroll
    for (int hh = 0; hh < 2; hh++)
        #pragma unroll
        for (int nt = 0; nt < 8; nt++)
            #pragma unroll
            for (int q = 0; q < 4; q++) O[hh][nt][q] = 0.f;

    float m_lo = -1e30f, m_hi = -1e30f, l_lo = 0.f, l_hi = 0.f;

    for (int kb = 0; kb < SQ; kb += 64) {
        __syncthreads();                  // prev PV done before overwriting K/Vt
        // ---- load + split K tiles (both heads) ----
        #pragma unroll
        for (int i = 0; i < 8; i++) {
            int idx = tid + (i << 8);
            int row = idx >> 5;
            int rem = idx & 31;
            int hh  = rem >> 4;
            int c   = (rem & 15) << 2;
            float4 a = *(const float4*)&g_K[(size_t)(kb + row) * EMB + c1 + (hh << 6) + c];
            unsigned h0,l0,h1,l1,h2,l2,h3,l3;
            tf_split(a.x,h0,l0); tf_split(a.y,h1,l1);
            tf_split(a.z,h2,l2); tf_split(a.w,h3,l3);
            int base = (hh*64 + row)*68 + c;
            *(float4*)&Kh[base] = make_float4(__uint_as_float(h0),__uint_as_float(h1),
                                              __uint_as_float(h2),__uint_as_float(h3));
            *(float4*)&Kl[base] = make_float4(__uint_as_float(l0),__uint_as_float(l1),
                                              __uint_as_float(l2),__uint_as_float(l3));
        }
        // ---- load V transposed + tf32-round ----
        #pragma unroll
        for (int i = 0; i < 8; i++) {
            int idx = tid + (i << 8);
            int row = idx & 63;
            int dg  = idx >> 6;           // 0..31
            float4 v = *(const float4*)&g_V[(size_t)(kb + row) * EMB + cv + (dg << 2)];
            Vt[(dg*4+0)*68 + row] = __uint_as_float(f2tf(v.x));
            Vt[(dg*4+1)*68 + row] = __uint_as_float(f2tf(v.y));
            Vt[(dg*4+2)*68 + row] = __uint_as_float(f2tf(v.z));
            Vt[(dg*4+3)*68 + row] = __uint_as_float(f2tf(v.w));
        }
        __syncthreads();

        // ---- S = Q_sel K_sel^T  (16 rows x 64 keys), 3xTF32, pure LDS+MMA ----
        float sacc[8][4];
        #pragma unroll
        for (int nt = 0; nt < 8; nt++)
            #pragma unroll
            for (int q = 0; q < 4; q++) sacc[nt][q] = 0.f;

        #pragma unroll
        for (int ks = 0; ks < 8; ks++) {
            const int kc = ks << 3;
            unsigned ah[4], al[4];
            ah[0] = __float_as_uint(Qhh[r_lo*68 + kc + t4]);
            ah[1] = __float_as_uint(Qhh[r_hi*68 + kc + t4]);
            ah[2] = __float_as_uint(Qhh[r_lo*68 + kc + t4 + 4]);
            ah[3] = __float_as_uint(Qhh[r_hi*68 + kc + t4 + 4]);
            al[0] = __float_as_uint(Qll[r_lo*68 + kc + t4]);
            al[1] = __float_as_uint(Qll[r_hi*68 + kc + t4]);
            al[2] = __float_as_uint(Qll[r_lo*68 + kc + t4 + 4]);
            al[3] = __float_as_uint(Qll[r_hi*68 + kc + t4 + 4]);
            #pragma unroll
            for (int nt = 0; nt < 8; nt++) {
                unsigned bh[2], bl[2];
                bh[0] = __float_as_uint(Khh[(nt*8+grp)*68 + kc + t4]);
                bh[1] = __float_as_uint(Khh[(nt*8+grp)*68 + kc + t4 + 4]);
                bl[0] = __float_as_uint(Kll[(nt*8+grp)*68 + kc + t4]);
                bl[1] = __float_as_uint(Kll[(nt*8+grp)*68 + kc + t4 + 4]);
                mma_tf32(sacc[nt], ah, bh);
                mma_tf32(sacc[nt], ah, bl);
                mma_tf32(sacc[nt], al, bh);
            }
        }

        // ---- online softmax (rows r_lo via c0/c1, r_hi via c2/c3) ----
        float mx_lo = -1e30f, mx_hi = -1e30f;
        #pragma unroll
        for (int nt = 0; nt < 8; nt++) {
            mx_lo = fmaxf(mx_lo, fmaxf(sacc[nt][0], sacc[nt][1]));
            mx_hi = fmaxf(mx_hi, fmaxf(sacc[nt][2], sacc[nt][3]));
        }
        mx_lo = fmaxf(mx_lo, __shfl_xor_sync(0xffffffffu, mx_lo, 1));
        mx_lo = fmaxf(mx_lo, __shfl_xor_sync(0xffffffffu, mx_lo, 2));
        mx_hi = fmaxf(mx_hi, __shfl_xor_sync(0xffffffffu, mx_hi, 1));
        mx_hi = fmaxf(mx_hi, __shfl_xor_sync(0xffffffffu, mx_hi, 2));
        const float mn_lo = fmaxf(m_lo, mx_lo);
        const float mn_hi = fmaxf(m_hi, mx_hi);
        const float sc_lo = __expf(m_lo - mn_lo);
        const float sc_hi = __expf(m_hi - mn_hi);
        float rs_lo = 0.f, rs_hi = 0.f;
        #pragma unroll
        for (int nt = 0; nt < 8; nt++) {
            float p0 = __expf(sacc[nt][0] - mn_lo);
            float p1 = __expf(sacc[nt][1] - mn_lo);
            float p2 = __expf(sacc[nt][2] - mn_hi);
            float p3 = __expf(sacc[nt][3] - mn_hi);
            rs_lo += p0 + p1;
            rs_hi += p2 + p3;
            int col = nt*8 + (t4 << 1);
            *(float2*)&Ph[r_lo*68 + col] =
                make_float2(__uint_as_float(f2tf(p0)), __uint_as_float(f2tf(p1)));
            *(float2*)&Ph[r_hi*68 + col] =
                make_float2(__uint_as_float(f2tf(p2)), __uint_as_float(f2tf(p3)));
        }
        rs_lo += __shfl_xor_sync(0xffffffffu, rs_lo, 1);
        rs_lo += __shfl_xor_sync(0xffffffffu, rs_lo, 2);
        rs_hi += __shfl_xor_sync(0xffffffffu, rs_hi, 1);
        rs_hi += __shfl_xor_sync(0xffffffffu, rs_hi, 2);
        l_lo = l_lo * sc_lo + rs_lo;  m_lo = mn_lo;
        l_hi = l_hi * sc_hi + rs_hi;  m_hi = mn_hi;
        if (t4 == 0) {
            scs[sel*64 + r_lo] = sc_lo;
            scs[sel*64 + r_hi] = sc_hi;
        }
        __syncthreads();

        // ---- PV: O[head] += P[head] * V  (this warp's V-half = sel) ----
        const float s1lo = scs[r_lo],      s1hi = scs[r_hi];
        const float s2lo = scs[64 + r_lo], s2hi = scs[64 + r_hi];
        #pragma unroll
        for (int hh = 0; hh < 2; hh++) {
            const float flo = hh ? s2lo : s1lo;
            const float fhi = hh ? s2hi : s1hi;
            #pragma unroll
            for (int nt = 0; nt < 8; nt++) {
                O[hh][nt][0] *= flo; O[hh][nt][1] *= flo;
                O[hh][nt][2] *= fhi; O[hh][nt][3] *= fhi;
            }
            const float* Pg = Ps + hh*64*68;
            #pragma unroll
            for (int ks = 0; ks < 8; ks++) {
                const int kc = ks << 3;
                unsigned a[4];
                a[0] = __float_as_uint(Pg[r_lo*68 + kc + t4]);
                a[1] = __float_as_uint(Pg[r_hi*68 + kc + t4]);
                a[2] = __float_as_uint(Pg[r_lo*68 + kc + t4 + 4]);
                a[3] = __float_as_uint(Pg[r_hi*68 + kc + t4 + 4]);
                #pragma unroll
                for (int nt = 0; nt < 8; nt++) {
                    unsigned b[2];
                    b[0] = __float_as_uint(Vt[(sel*64 + nt*8 + grp)*68 + kc + t4]);
                    b[1] = __float_as_uint(Vt[(sel*64 + nt*8 + grp)*68 + kc + t4 + 4]);
                    mma_tf32(O[hh][nt], a, b);
                }
            }
        }
    }

    // ---- epilogue: combine heads, RMSNorm over 128 dims, gain, scale ----
    if (t4 == 0) {
        ls[sel*64 + r_lo] = l_lo;
        ls[sel*64 + r_hi] = l_hi;
    }
    __syncthreads();
    const float lam   = g_lam;
    const float i1lo  = 1.f  / ls[r_lo],      i1hi = 1.f  / ls[r_hi];
    const float i2lo  = lam  / ls[64 + r_lo], i2hi = lam  / ls[64 + r_hi];
    float o[8][4], ss_lo = 0.f, ss_hi = 0.f;
    #pragma unroll
    for (int nt = 0; nt < 8; nt++) {
        o[nt][0] = O[0][nt][0]*i1lo - O[1][nt][0]*i2lo;
        o[nt][1] = O[0][nt][1]*i1lo - O[1][nt][1]*i2lo;
        o[nt][2] = O[0][nt][2]*i1hi - O[1][nt][2]*i2hi;
        o[nt][3] = O[0][nt][3]*i1hi - O[1][nt][3]*i2hi;
        ss_lo += o[nt][0]*o[nt][0] + o[nt][1]*o[nt][1];
        ss_hi += o[nt][2]*o[nt][2] + o[nt][3]*o[nt][3];
    }
    ss_lo += __shfl_xor_sync(0xffffffffu, ss_lo, 1);
    ss_lo += __shfl_xor_sync(0xffffffffu, ss_lo, 2);
    ss_hi += __shfl_xor_sync(0xffffffffu, ss_hi, 1);
    ss_hi += __shfl_xor_sync(0xffffffffu, ss_hi, 2);
    if (t4 == 0) {
        atomicAdd(&rss[r_lo], ss_lo);
        atomicAdd(&rss[r_hi], ss_hi);
    }
    __syncthreads();
    const float post_lo = rsqrtf(rss[r_lo] * (1.f/128.f) + 1e-5f) * (1.f - LAMBDA_INIT_F);
    const float post_hi = rsqrtf(rss[r_hi] * (1.f/128.f) + 1e-5f) * (1.f - LAMBDA_INIT_F);
    #pragma unroll
    for (int nt = 0; nt < 8; nt++) {
        int col = (sel << 6) + nt*8 + (t4 << 1);
        float g0 = gw[col], g1 = gw[col + 1];
        *(float2*)&g_A[(size_t)(qb + r_lo) * EMB + cv + col] =
            make_float2(o[nt][0]*post_lo*g0, o[nt][1]*post_lo*g1);
        *(float2*)&g_A[(size_t)(qb + r_hi) * EMB + cv + col] =
            make_float2(o[nt][2]*post_hi*g0, o[nt][3]*post_hi*g1);
    }
}

// ---------------------------------------------------------------------------
// kernel_launch
// ---------------------------------------------------------------------------
extern "C" void kernel_launch(void* const* d_in, const int* in_sizes, int n_in,
                              void* d_out, int out_size)
{
    const float* query = (const float*)d_in[0];
    const float* key_  = (const float*)d_in[1];
    const float* value = (const float*)d_in[2];
    // d_in[3] rel_pos, d_in[4] attn_mask — both no-ops here
    const float* Wq = (const float*)d_in[5];
    const float* Wk = (const float*)d_in[6];
    const float* Wv = (const float*)d_in[7];
    const float* Wo = (const float*)d_in[8];
    const float* lq1 = (const float*)d_in[9];
    const float* lk1 = (const float*)d_in[10];
    const float* lq2 = (const float*)d_in[11];
    const float* lk2 = (const float*)d_in[12];
    const float* gw  = (const float*)d_in[13];
    float* out = (float*)d_out;

    float *pQ, *pK, *pV, *pA;
    cudaGetSymbolAddress((void**)&pQ, g_Q);
    cudaGetSymbolAddress((void**)&pK, g_K);
    cudaGetSymbolAddress((void**)&pV, g_V);
    cudaGetSymbolAddress((void**)&pA, g_A);

    cudaFuncSetAttribute(gemm_tf32,
                         cudaFuncAttributeMaxDynamicSharedMemorySize, GEMM_SMEM_BYTES);
    cudaFuncSetAttribute(diffattn_tc,
                         cudaFuncAttributeMaxDynamicSharedMemorySize, ATT_SMEM_BYTES);

    lam_kernel<<<1, 32>>>(lq1, lk1, lq2, lk2);

    dim3 ggrid(SQ / 128, SQ / 128);
    gemm_tf32<<<ggrid, 256, GEMM_SMEM_BYTES>>>(query, Wq, pQ);
    gemm_tf32<<<ggrid, 256, GEMM_SMEM_BYTES>>>(key_,  Wk, pK);
    gemm_tf32<<<ggrid, 256, GEMM_SMEM_BYTES>>>(value, Wv, pV);

    dim3 agrid(SQ / 64, NH);
    diffattn_tc<<<agrid, 256, ATT_SMEM_BYTES>>>(gw);

    gemm_tf32<<<ggrid, 256, GEMM_SMEM_BYTES>>>(pA, Wo, out);
}

// round 11
// speedup vs baseline: 2.0649x; 1.0063x over previous
#include <cuda_runtime.h>
#include <cuda_bf16.h>
#include <math.h>

// Problem constants
#define SQ   2048          // sequence length (= M = N = K of all GEMMs)
#define EMB  2048
#define NH   16            // output heads
#define HD   64            // differential head dim
#define VD   128           // value head dim = 2*HD

// 0.8 - 0.6*exp(-0.3*12) as a compile-time literal (usable in device code)
#define LAMBDA_INIT_F 0.7836057665316245f

// ---------------------------------------------------------------------------
// Scratch (static __device__ allocations only — no cudaMalloc allowed)
// ---------------------------------------------------------------------------
__device__ float g_Q[SQ * EMB];
__device__ float g_K[SQ * EMB];
__device__ float g_V[SQ * EMB];
__device__ float g_A[SQ * EMB];   // post-attention, post-RMSNorm activations
__device__ float g_lam;           // lambda_full

// ---------------------------------------------------------------------------
// lambda_full = exp(sum lq1*lk1) - exp(sum lq2*lk2) + LAMBDA_INIT
// ---------------------------------------------------------------------------
__global__ void lam_kernel(const float* __restrict__ lq1, const float* __restrict__ lk1,
                           const float* __restrict__ lq2, const float* __restrict__ lk2)
{
    int t = threadIdx.x;   // 32 threads
    float a = lq1[t] * lk1[t] + lq1[t + 32] * lk1[t + 32];
    float b = lq2[t] * lk2[t] + lq2[t + 32] * lk2[t + 32];
    #pragma unroll
    for (int o = 16; o; o >>= 1) {
        a += __shfl_xor_sync(0xffffffffu, a, o);
        b += __shfl_xor_sync(0xffffffffu, b, o);
    }
    if (t == 0) g_lam = expf(a) - expf(b) + LAMBDA_INIT_F;
}

// ---------------------------------------------------------------------------
// tf32 helpers
// ---------------------------------------------------------------------------
__device__ __forceinline__ unsigned f2tf(float x) {
    unsigned r;
    asm("cvt.rna.tf32.f32 %0, %1;" : "=r"(r) : "f"(x));
    return r;
}

__device__ __forceinline__ void mma_tf32(float* d, const unsigned* a, const unsigned* b) {
    asm volatile(
        "mma.sync.aligned.m16n8k8.row.col.f32.tf32.tf32.f32 "
        "{%0,%1,%2,%3}, {%4,%5,%6,%7}, {%8,%9}, {%0,%1,%2,%3};"
        : "+f"(d[0]), "+f"(d[1]), "+f"(d[2]), "+f"(d[3])
        : "r"(a[0]), "r"(a[1]), "r"(a[2]), "r"(a[3]), "r"(b[0]), "r"(b[1]));
}

// Split x into tf32 hi + tf32 lo such that hi+lo ~= x to ~2^-22.
__device__ __forceinline__ void tf_split(float x, unsigned& hi, unsigned& lo) {
    hi = f2tf(x);
    lo = f2tf(x - __uint_as_float(hi));
}

// ---------------------------------------------------------------------------
// 3xTF32 GEMM with pre-split hi/lo smem planes + register prefetch pipeline.
// C[i,j] = sum_k A[i,k]*B[j,k].  128x128 tile, BK=32, 256 thr, warp tile 64x32.
// ---------------------------------------------------------------------------
#define GEMM_SMEM_BYTES (4 * 128 * 36 * 4)

__global__ __launch_bounds__(256, 2) void gemm_tf32(const float* __restrict__ A,
                                                    const float* __restrict__ B,
                                                    float* __restrict__ C)
{
    extern __shared__ float gsm[];
    float* Ah = gsm;                 // [128][36]
    float* Al = Ah + 128 * 36;
    float* Bh = Al + 128 * 36;
    float* Bl = Bh + 128 * 36;

    const int tid    = threadIdx.x;
    const int wid    = tid >> 5;
    const int lane   = tid & 31;
    const int warp_m = wid >> 2;            // 0..1  -> 64-row slab
    const int warp_n = wid & 3;             // 0..3  -> 32-col slab
    const int grp    = lane >> 2;           // 0..7
    const int t4     = lane & 3;            // 0..3
    const int bm     = blockIdx.y << 7;
    const int bn     = blockIdx.x << 7;

    // per-thread load coordinates (constant across iterations)
    const int ldr = tid >> 3;               // base row 0..31 (+32 per i)
    const int ldc = (tid & 7) << 2;         // col within BK
    const float* Abase = A + (size_t)(bm + ldr) * SQ + ldc;
    const float* Bbase = B + (size_t)(bn + ldr) * SQ + ldc;

    float acc[4][4][4];
    #pragma unroll
    for (int i = 0; i < 4; i++)
        #pragma unroll
        for (int j = 0; j < 4; j++)
            #pragma unroll
            for (int q = 0; q < 4; q++) acc[i][j][q] = 0.f;

    // ---- prologue: prefetch first tile into registers ----
    float4 va[4], vb[4];
    #pragma unroll
    for (int i = 0; i < 4; i++) {
        va[i] = *(const float4*)(Abase + (size_t)(i * 32) * SQ);
        vb[i] = *(const float4*)(Bbase + (size_t)(i * 32) * SQ);
    }

    for (int k0 = 0; k0 < SQ; k0 += 32) {
        // ---- split + store the prefetched tile ----
        #pragma unroll
        for (int i = 0; i < 4; i++) {
            int row = ldr + (i << 5);
            unsigned h0,l0,h1,l1,h2,l2,h3,l3;
            tf_split(va[i].x,h0,l0); tf_split(va[i].y,h1,l1);
            tf_split(va[i].z,h2,l2); tf_split(va[i].w,h3,l3);
            *(float4*)&Ah[row*36+ldc] = make_float4(__uint_as_float(h0),__uint_as_float(h1),
                                                    __uint_as_float(h2),__uint_as_float(h3));
            *(float4*)&Al[row*36+ldc] = make_float4(__uint_as_float(l0),__uint_as_float(l1),
                                                    __uint_as_float(l2),__uint_as_float(l3));
            tf_split(vb[i].x,h0,l0); tf_split(vb[i].y,h1,l1);
            tf_split(vb[i].z,h2,l2); tf_split(vb[i].w,h3,l3);
            *(float4*)&Bh[row*36+ldc] = make_float4(__uint_as_float(h0),__uint_as_float(h1),
                                                    __uint_as_float(h2),__uint_as_float(h3));
            *(float4*)&Bl[row*36+ldc] = make_float4(__uint_as_float(l0),__uint_as_float(l1),
                                                    __uint_as_float(l2),__uint_as_float(l3));
        }
        __syncthreads();

        // ---- prefetch next tile (latency hidden behind the MMA block) ----
        if (k0 + 32 < SQ) {
            #pragma unroll
            for (int i = 0; i < 4; i++) {
                va[i] = *(const float4*)(Abase + (size_t)(i * 32) * SQ + k0 + 32);
                vb[i] = *(const float4*)(Bbase + (size_t)(i * 32) * SQ + k0 + 32);
            }
        }

        #pragma unroll
        for (int kc = 0; kc < 4; kc++) {
            const int kb = kc << 3;
            unsigned bh[4][2], bl[4][2];
            #pragma unroll
            for (int nt = 0; nt < 4; nt++) {
                int col = (warp_n << 5) + (nt << 3) + grp;
                bh[nt][0] = __float_as_uint(Bh[col*36 + kb + t4]);
                bh[nt][1] = __float_as_uint(Bh[col*36 + kb + t4 + 4]);
                bl[nt][0] = __float_as_uint(Bl[col*36 + kb + t4]);
                bl[nt][1] = __float_as_uint(Bl[col*36 + kb + t4 + 4]);
            }
            #pragma unroll
            for (int mt = 0; mt < 4; mt++) {
                int rbase = (warp_m << 6) + (mt << 4);
                unsigned ah[4], al[4];
                ah[0] = __float_as_uint(Ah[(rbase+grp)*36   + kb + t4]);
                ah[1] = __float_as_uint(Ah[(rbase+grp+8)*36 + kb + t4]);
                ah[2] = __float_as_uint(Ah[(rbase+grp)*36   + kb + t4 + 4]);
                ah[3] = __float_as_uint(Ah[(rbase+grp+8)*36 + kb + t4 + 4]);
                al[0] = __float_as_uint(Al[(rbase+grp)*36   + kb + t4]);
                al[1] = __float_as_uint(Al[(rbase+grp+8)*36 + kb + t4]);
                al[2] = __float_as_uint(Al[(rbase+grp)*36   + kb + t4 + 4]);
                al[3] = __float_as_uint(Al[(rbase+grp+8)*36 + kb + t4 + 4]);
                #pragma unroll
                for (int nt = 0; nt < 4; nt++) {
                    mma_tf32(acc[mt][nt], ah, bh[nt]);
                    mma_tf32(acc[mt][nt], ah, bl[nt]);
                    mma_tf32(acc[mt][nt], al, bh[nt]);
                }
            }
        }
        __syncthreads();
    }

    #pragma unroll
    for (int mt = 0; mt < 4; mt++) {
        int row0 = bm + (warp_m << 6) + (mt << 4) + grp;
        #pragma unroll
        for (int nt = 0; nt < 4; nt++) {
            int col = bn + (warp_n << 5) + (nt << 3) + (t4 << 1);
            *(float2*)(C + (size_t)row0 * SQ + col)       = make_float2(acc[mt][nt][0], acc[mt][nt][1]);
            *(float2*)(C + (size_t)(row0 + 8) * SQ + col) = make_float2(acc[mt][nt][2], acc[mt][nt][3]);
        }
    }
}

// ---------------------------------------------------------------------------
// Tensor-core differential flash-attention + fused RMSNorm, with K/V register
// prefetch (occ is smem-bound at 1 block, so the extra registers are free).
// Grid (SQ/64, NH), 256 threads (8 warps).
// ---------------------------------------------------------------------------
#define ATT_SMEM_FLOATS (6*64*2*68 + 128 + 128 + 64)
#define ATT_SMEM_BYTES  (ATT_SMEM_FLOATS * 4)

__global__ __launch_bounds__(256) void diffattn_tc(const float* __restrict__ gw)
{
    extern __shared__ float sm[];
    float* Qh  = sm;                  // [2][64][68]  Q hi plane (scaled)
    float* Ql  = Qh  + 2*64*68;       // [2][64][68]  Q lo plane
    float* Kh  = Ql  + 2*64*68;       // [2][64][68]  K hi plane
    float* Kl  = Kh  + 2*64*68;       // [2][64][68]  K lo plane
    float* Vt  = Kl  + 2*64*68;       // [128][68]    transposed, tf32-rounded
    float* Ps  = Vt  + 128*68;        // [2][64][68]  probs, tf32-rounded
    float* scs = Ps  + 2*64*68;       // [2][64]      per-tile rescale factors
    float* ls  = scs + 128;           // [2][64]      final softmax denominators
    float* rss = ls  + 128;           // [64]         row sum-of-squares

    const int h   = blockIdx.y;
    const int qb  = blockIdx.x << 6;      // 64 query rows
    const int c1  = h << 7;               // Q/K cols: head1 at +0, head2 at +64
    const int cv  = h << 7;               // V cols

    const int tid  = threadIdx.x;
    const int wid  = tid >> 5;
    const int lane = tid & 31;
    const int grp  = lane >> 2;           // 0..7
    const int t4   = lane & 3;            // 0..3
    const int slab = wid >> 1;            // 0..3 : rows slab*16 .. +15
    const int sel  = wid & 1;             // S-phase head / PV-phase V-half
    const int r_lo = slab*16 + grp;       // this lane's two fragment rows
    const int r_hi = r_lo + 8;

    if (tid < 64) rss[tid] = 0.f;

    // per-thread K/V load coordinates (constant across iterations)
    const int krow0 = tid >> 5;           // 0..7 (+8 per i)
    const int khh   = (tid & 31) >> 4;    // 0/1
    const int kc0   = (tid & 15) << 2;
    const int vrow  = tid & 63;
    const int vdg0  = tid >> 6;           // 0..3 (+4 per i)

    // ---- load + scale + split Q (both heads) once ----
    const float qscale = 0.125f;
    #pragma unroll
    for (int i = 0; i < 8; i++) {
        int idx = tid + (i << 8);         // 0..2047 float4s
        int row = idx >> 5;
        int rem = idx & 31;
        int hh  = rem >> 4;
        int c   = (rem & 15) << 2;
        float4 a = *(const float4*)&g_Q[(size_t)(qb + row) * EMB + c1 + (hh << 6) + c];
        unsigned h0,l0,h1,l1,h2,l2,h3,l3;
        tf_split(a.x*qscale,h0,l0); tf_split(a.y*qscale,h1,l1);
        tf_split(a.z*qscale,h2,l2); tf_split(a.w*qscale,h3,l3);
        int base = (hh*64 + row)*68 + c;
        *(float4*)&Qh[base] = make_float4(__uint_as_float(h0),__uint_as_float(h1),
                                          __uint_as_float(h2),__uint_as_float(h3));
        *(float4*)&Ql[base] = make_float4(__uint_as_float(l0),__uint_as_float(l1),
                                          __uint_as_float(l2),__uint_as_float(l3));
    }

    // ---- prologue: prefetch first K/V tiles into registers ----
    float4 kq[8], vq[8];
    #pragma unroll
    for (int i = 0; i < 8; i++) {
        kq[i] = *(const float4*)&g_K[(size_t)(krow0 + (i << 3)) * EMB + c1 + (khh << 6) + kc0];
        vq[i] = *(const float4*)&g_V[(size_t)vrow * EMB + cv + ((vdg0 + (i << 2)) << 2)];
    }

    const float* Qhh = Qh + sel*64*68;
    const float* Qll = Ql + sel*64*68;
    const float* Khh = Kh + sel*64*68;
    const float* Kll = Kl + sel*64*68;
    float*       Ph  = Ps + sel*64*68;

    float O[2][8][4];                     // [head][nt][frag], V cols sel*64 + nt*8 + 2*t4
    #pragma unroll
    for (int hh = 0; hh < 2; hh++)
        #pragma unroll
        for (int nt = 0; nt < 8; nt++)
            #pragma unroll
            for (int q = 0; q < 4; q++) O[hh][nt][q] = 0.f;

    float m_lo = -1e30f, m_hi = -1e30f, l_lo = 0.f, l_hi = 0.f;

    for (int kb = 0; kb < SQ; kb += 64) {
        __syncthreads();                  // prev PV done before overwriting K/Vt
        // ---- split + store prefetched K tiles (both heads) ----
        #pragma unroll
        for (int i = 0; i < 8; i++) {
            int row = krow0 + (i << 3);
            unsigned h0,l0,h1,l1,h2,l2,h3,l3;
            tf_split(kq[i].x,h0,l0); tf_split(kq[i].y,h1,l1);
            tf_split(kq[i].z,h2,l2); tf_split(kq[i].w,h3,l3);
            int base = (khh*64 + row)*68 + kc0;
            *(float4*)&Kh[base] = make_float4(__uint_as_float(h0),__uint_as_float(h1),
                                              __uint_as_float(h2),__uint_as_float(h3));
            *(float4*)&Kl[base] = make_float4(__uint_as_float(l0),__uint_as_float(l1),
                                              __uint_as_float(l2),__uint_as_float(l3));
        }
        // ---- store prefetched V transposed + tf32-round ----
        #pragma unroll
        for (int i = 0; i < 8; i++) {
            int dg = vdg0 + (i << 2);
            Vt[(dg*4+0)*68 + vrow] = __uint_as_float(f2tf(vq[i].x));
            Vt[(dg*4+1)*68 + vrow] = __uint_as_float(f2tf(vq[i].y));
            Vt[(dg*4+2)*68 + vrow] = __uint_as_float(f2tf(vq[i].z));
            Vt[(dg*4+3)*68 + vrow] = __uint_as_float(f2tf(vq[i].w));
        }
        __syncthreads();

        // ---- prefetch next K/V tiles (latency hidden behind S+softmax+PV) ----
        if (kb + 64 < SQ) {
            #pragma unroll
            for (int i = 0; i < 8; i++) {
                kq[i] = *(const float4*)&g_K[(size_t)(kb + 64 + krow0 + (i << 3)) * EMB
                                             + c1 + (khh << 6) + kc0];
                vq[i] = *(const float4*)&g_V[(size_t)(kb + 64 + vrow) * EMB
                                             + cv + ((vdg0 + (i << 2)) << 2)];
            }
        }

        // ---- S = Q_sel K_sel^T  (16 rows x 64 keys), 3xTF32, pure LDS+MMA ----
        float sacc[8][4];
        #pragma unroll
        for (int nt = 0; nt < 8; nt++)
            #pragma unroll
            for (int q = 0; q < 4; q++) sacc[nt][q] = 0.f;

        #pragma unroll
        for (int ks = 0; ks < 8; ks++) {
            const int kc = ks << 3;
            unsigned ah[4], al[4];
            ah[0] = __float_as_uint(Qhh[r_lo*68 + kc + t4]);
            ah[1] = __float_as_uint(Qhh[r_hi*68 + kc + t4]);
            ah[2] = __float_as_uint(Qhh[r_lo*68 + kc + t4 + 4]);
            ah[3] = __float_as_uint(Qhh[r_hi*68 + kc + t4 + 4]);
            al[0] = __float_as_uint(Qll[r_lo*68 + kc + t4]);
            al[1] = __float_as_uint(Qll[r_hi*68 + kc + t4]);
            al[2] = __float_as_uint(Qll[r_lo*68 + kc + t4 + 4]);
            al[3] = __float_as_uint(Qll[r_hi*68 + kc + t4 + 4]);
            #pragma unroll
            for (int nt = 0; nt < 8; nt++) {
                unsigned bh[2], bl[2];
                bh[0] = __float_as_uint(Khh[(nt*8+grp)*68 + kc + t4]);
                bh[1] = __float_as_uint(Khh[(nt*8+grp)*68 + kc + t4 + 4]);
                bl[0] = __float_as_uint(Kll[(nt*8+grp)*68 + kc + t4]);
                bl[1] = __float_as_uint(Kll[(nt*8+grp)*68 + kc + t4 + 4]);
                mma_tf32(sacc[nt], ah, bh);
                mma_tf32(sacc[nt], ah, bl);
                mma_tf32(sacc[nt], al, bh);
            }
        }

        // ---- online softmax (rows r_lo via c0/c1, r_hi via c2/c3) ----
        float mx_lo = -1e30f, mx_hi = -1e30f;
        #pragma unroll
        for (int nt = 0; nt < 8; nt++) {
            mx_lo = fmaxf(mx_lo, fmaxf(sacc[nt][0], sacc[nt][1]));
            mx_hi = fmaxf(mx_hi, fmaxf(sacc[nt][2], sacc[nt][3]));
        }
        mx_lo = fmaxf(mx_lo, __shfl_xor_sync(0xffffffffu, mx_lo, 1));
        mx_lo = fmaxf(mx_lo, __shfl_xor_sync(0xffffffffu, mx_lo, 2));
        mx_hi = fmaxf(mx_hi, __shfl_xor_sync(0xffffffffu, mx_hi, 1));
        mx_hi = fmaxf(mx_hi, __shfl_xor_sync(0xffffffffu, mx_hi, 2));
        const float mn_lo = fmaxf(m_lo, mx_lo);
        const float mn_hi = fmaxf(m_hi, mx_hi);
        const float sc_lo = __expf(m_lo - mn_lo);
        const float sc_hi = __expf(m_hi - mn_hi);
        float rs_lo = 0.f, rs_hi = 0.f;
        #pragma unroll
        for (int nt = 0; nt < 8; nt++) {
            float p0 = __expf(sacc[nt][0] - mn_lo);
            float p1 = __expf(sacc[nt][1] - mn_lo);
            float p2 = __expf(sacc[nt][2] - mn_hi);
            float p3 = __expf(sacc[nt][3] - mn_hi);
            rs_lo += p0 + p1;
            rs_hi += p2 + p3;
            int col = nt*8 + (t4 << 1);
            *(float2*)&Ph[r_lo*68 + col] =
                make_float2(__uint_as_float(f2tf(p0)), __uint_as_float(f2tf(p1)));
            *(float2*)&Ph[r_hi*68 + col] =
                make_float2(__uint_as_float(f2tf(p2)), __uint_as_float(f2tf(p3)));
        }
        rs_lo += __shfl_xor_sync(0xffffffffu, rs_lo, 1);
        rs_lo += __shfl_xor_sync(0xffffffffu, rs_lo, 2);
        rs_hi += __shfl_xor_sync(0xffffffffu, rs_hi, 1);
        rs_hi += __shfl_xor_sync(0xffffffffu, rs_hi, 2);
        l_lo = l_lo * sc_lo + rs_lo;  m_lo = mn_lo;
        l_hi = l_hi * sc_hi + rs_hi;  m_hi = mn_hi;
        if (t4 == 0) {
            scs[sel*64 + r_lo] = sc_lo;
            scs[sel*64 + r_hi] = sc_hi;
        }
        __syncthreads();

        // ---- PV: O[head] += P[head] * V  (this warp's V-half = sel) ----
        const float s1lo = scs[r_lo],      s1hi = scs[r_hi];
        const float s2lo = scs[64 + r_lo], s2hi = scs[64 + r_hi];
        #pragma unroll
        for (int hh = 0; hh < 2; hh++) {
            const float flo = hh ? s2lo : s1lo;
            const float fhi = hh ? s2hi : s1hi;
            #pragma unroll
            for (int nt = 0; nt < 8; nt++) {
                O[hh][nt][0] *= flo; O[hh][nt][1] *= flo;
                O[hh][nt][2] *= fhi; O[hh][nt][3] *= fhi;
            }
            const float* Pg = Ps + hh*64*68;
            #pragma unroll
            for (int ks = 0; ks < 8; ks++) {
                const int kc = ks << 3;
                unsigned a[4];
                a[0] = __float_as_uint(Pg[r_lo*68 + kc + t4]);
                a[1] = __float_as_uint(Pg[r_hi*68 + kc + t4]);
                a[2] = __float_as_uint(Pg[r_lo*68 + kc + t4 + 4]);
                a[3] = __float_as_uint(Pg[r_hi*68 + kc + t4 + 4]);
                #pragma unroll
                for (int nt = 0; nt < 8; nt++) {
                    unsigned b[2];
                    b[0] = __float_as_uint(Vt[(sel*64 + nt*8 + grp)*68 + kc + t4]);
                    b[1] = __float_as_uint(Vt[(sel*64 + nt*8 + grp)*68 + kc + t4 + 4]);
                    mma_tf32(O[hh][nt], a, b);
                }
            }
        }
    }

    // ---- epilogue: combine heads, RMSNorm over 128 dims, gain, scale ----
    if (t4 == 0) {
        ls[sel*64 + r_lo] = l_lo;
        ls[sel*64 + r_hi] = l_hi;
    }
    __syncthreads();
    const float lam   = g_lam;
    const float i1lo  = 1.f  / ls[r_lo],      i1hi = 1.f  / ls[r_hi];
    const float i2lo  = lam  / ls[64 + r_lo], i2hi = lam  / ls[64 + r_hi];
    float o[8][4], ss_lo = 0.f, ss_hi = 0.f;
    #pragma unroll
    for (int nt = 0; nt < 8; nt++) {
        o[nt][0] = O[0][nt][0]*i1lo - O[1][nt][0]*i2lo;
        o[nt][1] = O[0][nt][1]*i1lo - O[1][nt][1]*i2lo;
        o[nt][2] = O[0][nt][2]*i1hi - O[1][nt][2]*i2hi;
        o[nt][3] = O[0][nt][3]*i1hi - O[1][nt][3]*i2hi;
        ss_lo += o[nt][0]*o[nt][0] + o[nt][1]*o[nt][1];
        ss_hi += o[nt][2]*o[nt][2] + o[nt][3]*o[nt][3];
    }
    ss_lo += __shfl_xor_sync(0xffffffffu, ss_lo, 1);
    ss_lo += __shfl_xor_sync(0xffffffffu, ss_lo, 2);
    ss_hi += __shfl_xor_sync(0xffffffffu, ss_hi, 1);
    ss_hi += __shfl_xor_sync(0xffffffffu, ss_hi, 2);
    if (t4 == 0) {
        atomicAdd(&rss[r_lo], ss_lo);
        atomicAdd(&rss[r_hi], ss_hi);
    }
    __syncthreads();
    const float post_lo = rsqrtf(rss[r_lo] * (1.f/128.f) + 1e-5f) * (1.f - LAMBDA_INIT_F);
    const float post_hi = rsqrtf(rss[r_hi] * (1.f/128.f) + 1e-5f) * (1.f - LAMBDA_INIT_F);
    #pragma unroll
    for (int nt = 0; nt < 8; nt++) {
        int col = (sel << 6) + nt*8 + (t4 << 1);
        float g0 = gw[col], g1 = gw[col + 1];
        *(float2*)&g_A[(size_t)(qb + r_lo) * EMB + cv + col] =
            make_float2(o[nt][0]*post_lo*g0, o[nt][1]*post_lo*g1);
        *(float2*)&g_A[(size_t)(qb + r_hi) * EMB + cv + col] =
            make_float2(o[nt][2]*post_hi*g0, o[nt][3]*post_hi*g1);
    }
}

// ---------------------------------------------------------------------------
// kernel_launch
// ---------------------------------------------------------------------------
extern "C" void kernel_launch(void* const* d_in, const int* in_sizes, int n_in,
                              void* d_out, int out_size)
{
    const float* query = (const float*)d_in[0];
    const float* key_  = (const float*)d_in[1];
    const float* value = (const float*)d_in[2];
    // d_in[3] rel_pos, d_in[4] attn_mask — both no-ops here
    const float* Wq = (const float*)d_in[5];
    const float* Wk = (const float*)d_in[6];
    const float* Wv = (const float*)d_in[7];
    const float* Wo = (const float*)d_in[8];
    const float* lq1 = (const float*)d_in[9];
    const float* lk1 = (const float*)d_in[10];
    const float* lq2 = (const float*)d_in[11];
    const float* lk2 = (const float*)d_in[12];
    const float* gw  = (const float*)d_in[13];
    float* out = (float*)d_out;

    float *pQ, *pK, *pV, *pA;
    cudaGetSymbolAddress((void**)&pQ, g_Q);
    cudaGetSymbolAddress((void**)&pK, g_K);
    cudaGetSymbolAddress((void**)&pV, g_V);
    cudaGetSymbolAddress((void**)&pA, g_A);

    cudaFuncSetAttribute(gemm_tf32,
                         cudaFuncAttributeMaxDynamicSharedMemorySize, GEMM_SMEM_BYTES);
    cudaFuncSetAttribute(diffattn_tc,
                         cudaFuncAttributeMaxDynamicSharedMemorySize, ATT_SMEM_BYTES);

    lam_kernel<<<1, 32>>>(lq1, lk1, lq2, lk2);

    dim3 ggrid(SQ / 128, SQ / 128);
    gemm_tf32<<<ggrid, 256, GEMM_SMEM_BYTES>>>(query, Wq, pQ);
    gemm_tf32<<<ggrid, 256, GEMM_SMEM_BYTES>>>(key_,  Wk, pK);
    gemm_tf32<<<ggrid, 256, GEMM_SMEM_BYTES>>>(value, Wv, pV);

    dim3 agrid(SQ / 64, NH);
    diffattn_tc<<<agrid, 256, ATT_SMEM_BYTES>>>(gw);

    gemm_tf32<<<ggrid, 256, GEMM_SMEM_BYTES>>>(pA, Wo, out);
}

// round 15
// speedup vs baseline: 3.0163x; 1.4608x over previous
#include <cuda_runtime.h>
#include <cuda_bf16.h>
#include <math.h>

// Problem constants
#define SQ   2048          // sequence length (= M = N = K of all GEMMs)
#define EMB  2048
#define NH   16            // output heads
#define HD   64            // differential head dim
#define VD   128           // value head dim = 2*HD

// 0.8 - 0.6*exp(-0.3*12) as a compile-time literal (usable in device code)
#define LAMBDA_INIT_F 0.7836057665316245f

// ---------------------------------------------------------------------------
// Scratch (static __device__ allocations only — no cudaMalloc allowed)
// ---------------------------------------------------------------------------
__device__ float g_Q[SQ * EMB];
__device__ float g_K[SQ * EMB];
__device__ float g_V[SQ * EMB];
__device__ float g_A[SQ * EMB];   // post-attention, post-RMSNorm activations
__device__ float g_lam;           // lambda_full

// ---------------------------------------------------------------------------
// lambda_full = exp(sum lq1*lk1) - exp(sum lq2*lk2) + LAMBDA_INIT
// ---------------------------------------------------------------------------
__global__ void lam_kernel(const float* __restrict__ lq1, const float* __restrict__ lk1,
                           const float* __restrict__ lq2, const float* __restrict__ lk2)
{
    int t = threadIdx.x;   // 32 threads
    float a = lq1[t] * lk1[t] + lq1[t + 32] * lk1[t + 32];
    float b = lq2[t] * lk2[t] + lq2[t + 32] * lk2[t + 32];
    #pragma unroll
    for (int o = 16; o; o >>= 1) {
        a += __shfl_xor_sync(0xffffffffu, a, o);
        b += __shfl_xor_sync(0xffffffffu, b, o);
    }
    if (t == 0) g_lam = expf(a) - expf(b) + LAMBDA_INIT_F;
}

// ---------------------------------------------------------------------------
// helpers
// ---------------------------------------------------------------------------
__device__ __forceinline__ unsigned f2tf(float x) {
    unsigned r;
    asm("cvt.rna.tf32.f32 %0, %1;" : "=r"(r) : "f"(x));
    return r;
}

__device__ __forceinline__ void mma_tf32(float* d, const unsigned* a, const unsigned* b) {
    asm volatile(
        "mma.sync.aligned.m16n8k8.row.col.f32.tf32.tf32.f32 "
        "{%0,%1,%2,%3}, {%4,%5,%6,%7}, {%8,%9}, {%0,%1,%2,%3};"
        : "+f"(d[0]), "+f"(d[1]), "+f"(d[2]), "+f"(d[3])
        : "r"(a[0]), "r"(a[1]), "r"(a[2]), "r"(a[3]), "r"(b[0]), "r"(b[1]));
}

__device__ __forceinline__ void mma_bf16(float* d, const unsigned* a, const unsigned* b) {
    asm volatile(
        "mma.sync.aligned.m16n8k16.row.col.f32.bf16.bf16.f32 "
        "{%0,%1,%2,%3}, {%4,%5,%6,%7}, {%8,%9}, {%0,%1,%2,%3};"
        : "+f"(d[0]), "+f"(d[1]), "+f"(d[2]), "+f"(d[3])
        : "r"(a[0]), "r"(a[1]), "r"(a[2]), "r"(a[3]), "r"(b[0]), "r"(b[1]));
}

// Split (x0,x1) into packed-bf16x2 hi and lo words: hi+lo ~= x to ~16-17 bits.
__device__ __forceinline__ void split_pack(float x0, float x1, unsigned& hi, unsigned& lo) {
    __nv_bfloat16 h0 = __float2bfloat16_rn(x0);
    __nv_bfloat16 h1 = __float2bfloat16_rn(x1);
    __nv_bfloat16 l0 = __float2bfloat16_rn(x0 - __bfloat162float(h0));
    __nv_bfloat16 l1 = __float2bfloat16_rn(x1 - __bfloat162float(h1));
    __nv_bfloat162 H = __halves2bfloat162(h0, h1);
    __nv_bfloat162 L = __halves2bfloat162(l0, l1);
    hi = *reinterpret_cast<unsigned*>(&H);
    lo = *reinterpret_cast<unsigned*>(&L);
}

// ---------------------------------------------------------------------------
// bf16x3 (Markidis) GEMM:  C[i,j] = sum_k A[i,k]*B[j,k]
// 128x128 tile, BK=32 (2 x k16 chunks), 256 thr, warp tile 64x32.
// smem planes hold packed bf16x2 pairs, stride 20 words (conflict-free).
// ---------------------------------------------------------------------------
#define GEMM_SMEM_BYTES (4 * 128 * 20 * 4)

__global__ __launch_bounds__(256, 2) void gemm_bf16x3(const float* __restrict__ A,
                                                      const float* __restrict__ B,
                                                      float* __restrict__ C)
{
    extern __shared__ unsigned gsm_u[];
    unsigned* Ah = gsm_u;            // [128][20] packed bf16x2 (16 pairs + pad)
    unsigned* Al = Ah + 128 * 20;
    unsigned* Bh = Al + 128 * 20;
    unsigned* Bl = Bh + 128 * 20;

    const int tid    = threadIdx.x;
    const int wid    = tid >> 5;
    const int lane   = tid & 31;
    const int warp_m = wid >> 2;            // 0..1  -> 64-row slab
    const int warp_n = wid & 3;             // 0..3  -> 32-col slab
    const int grp    = lane >> 2;           // 0..7
    const int t4     = lane & 3;            // 0..3
    const int bm     = blockIdx.y << 7;
    const int bn     = blockIdx.x << 7;

    float acc[4][4][4];
    #pragma unroll
    for (int i = 0; i < 4; i++)
        #pragma unroll
        for (int j = 0; j < 4; j++)
            #pragma unroll
            for (int q = 0; q < 4; q++) acc[i][j][q] = 0.f;

    for (int k0 = 0; k0 < SQ; k0 += 32) {
        #pragma unroll
        for (int i = 0; i < 4; i++) {
            int idx = tid + (i << 8);
            int row = idx >> 3;
            int c   = (idx & 7) << 2;       // col 0..28 step 4
            int pc  = c >> 1;               // pair index (even)
            unsigned h01, l01, h23, l23;
            float4 va = *(const float4*)(A + (size_t)(bm + row) * SQ + k0 + c);
            split_pack(va.x, va.y, h01, l01);
            split_pack(va.z, va.w, h23, l23);
            *(uint2*)&Ah[row * 20 + pc] = make_uint2(h01, h23);
            *(uint2*)&Al[row * 20 + pc] = make_uint2(l01, l23);
            float4 vb = *(const float4*)(B + (size_t)(bn + row) * SQ + k0 + c);
            split_pack(vb.x, vb.y, h01, l01);
            split_pack(vb.z, vb.w, h23, l23);
            *(uint2*)&Bh[row * 20 + pc] = make_uint2(h01, h23);
            *(uint2*)&Bl[row * 20 + pc] = make_uint2(l01, l23);
        }
        __syncthreads();

        #pragma unroll
        for (int kc = 0; kc < 2; kc++) {    // two k16 chunks
            const int kb = kc << 3;         // pair offset
            unsigned bh[4][2], bl[4][2];
            #pragma unroll
            for (int nt = 0; nt < 4; nt++) {
                int col = (warp_n << 5) + (nt << 3) + grp;
                bh[nt][0] = Bh[col*20 + kb + t4];
                bh[nt][1] = Bh[col*20 + kb + t4 + 4];
                bl[nt][0] = Bl[col*20 + kb + t4];
                bl[nt][1] = Bl[col*20 + kb + t4 + 4];
            }
            #pragma unroll
            for (int mt = 0; mt < 4; mt++) {
                int rbase = (warp_m << 6) + (mt << 4);
                unsigned ah[4], al[4];
                ah[0] = Ah[(rbase+grp)*20   + kb + t4];
                ah[1] = Ah[(rbase+grp+8)*20 + kb + t4];
                ah[2] = Ah[(rbase+grp)*20   + kb + t4 + 4];
                ah[3] = Ah[(rbase+grp+8)*20 + kb + t4 + 4];
                al[0] = Al[(rbase+grp)*20   + kb + t4];
                al[1] = Al[(rbase+grp+8)*20 + kb + t4];
                al[2] = Al[(rbase+grp)*20   + kb + t4 + 4];
                al[3] = Al[(rbase+grp+8)*20 + kb + t4 + 4];
                #pragma unroll
                for (int nt = 0; nt < 4; nt++) {
                    mma_bf16(acc[mt][nt], ah, bh[nt]);   // hi*hi
                    mma_bf16(acc[mt][nt], ah, bl[nt]);   // hi*lo
                    mma_bf16(acc[mt][nt], al, bh[nt]);   // lo*hi
                }
            }
        }
        __syncthreads();
    }

    #pragma unroll
    for (int mt = 0; mt < 4; mt++) {
        int row0 = bm + (warp_m << 6) + (mt << 4) + grp;
        #pragma unroll
        for (int nt = 0; nt < 4; nt++) {
            int col = bn + (warp_n << 5) + (nt << 3) + (t4 << 1);
            *(float2*)(C + (size_t)row0 * SQ + col)       = make_float2(acc[mt][nt][0], acc[mt][nt][1]);
            *(float2*)(C + (size_t)(row0 + 8) * SQ + col) = make_float2(acc[mt][nt][2], acc[mt][nt][3]);
        }
    }
}

// ---------------------------------------------------------------------------
// Tensor-core differential flash-attention + fused RMSNorm.
// QK on bf16x3 m16n8k16 (halved S-phase tensor time); PV stays 1xTF32.
// Grid (SQ/64, NH), 256 threads (8 warps). K/V register prefetch retained.
// ---------------------------------------------------------------------------
#define ATT_SMEM_WORDS (4*2*64*36 + 128*68 + 2*64*68 + 128 + 128 + 64)
#define ATT_SMEM_BYTES (ATT_SMEM_WORDS * 4)

__global__ __launch_bounds__(256) void diffattn_tc(const float* __restrict__ gw)
{
    extern __shared__ float sm[];
    unsigned* Qh = (unsigned*)sm;         // [2][64][36] packed bf16x2 (32 pairs + pad)
    unsigned* Ql = Qh + 2*64*36;
    unsigned* Kh = Ql + 2*64*36;
    unsigned* Kl = Kh + 2*64*36;
    float* Vt  = (float*)(Kl + 2*64*36);  // [128][68]  transposed, tf32-rounded
    float* Ps  = Vt  + 128*68;            // [2][64][68] probs, tf32-rounded
    float* scs = Ps  + 2*64*68;           // [2][64]
    float* ls  = scs + 128;               // [2][64]
    float* rss = ls  + 128;               // [64]

    const int h   = blockIdx.y;
    const int qb  = blockIdx.x << 6;      // 64 query rows
    const int c1  = h << 7;               // Q/K cols: head1 at +0, head2 at +64
    const int cv  = h << 7;               // V cols

    const int tid  = threadIdx.x;
    const int wid  = tid >> 5;
    const int lane = tid & 31;
    const int grp  = lane >> 2;           // 0..7
    const int t4   = lane & 3;            // 0..3
    const int slab = wid >> 1;            // 0..3 : rows slab*16 .. +15
    const int sel  = wid & 1;             // S-phase head / PV-phase V-half
    const int r_lo = slab*16 + grp;
    const int r_hi = r_lo + 8;

    if (tid < 64) rss[tid] = 0.f;

    // per-thread K/V load coordinates (constant across iterations)
    const int krow0 = tid >> 5;           // 0..7 (+8 per i)
    const int khh   = (tid & 31) >> 4;    // 0/1
    const int kc0   = (tid & 15) << 2;    // col 0..60 step 4
    const int vrow  = tid & 63;
    const int vdg0  = tid >> 6;           // 0..3 (+4 per i)

    // ---- load + scale + split Q (both heads) once ----
    const float qscale = 0.125f;
    #pragma unroll
    for (int i = 0; i < 8; i++) {
        int idx = tid + (i << 8);         // 0..2047 float4s
        int row = idx >> 5;
        int rem = idx & 31;
        int hh  = rem >> 4;
        int c   = (rem & 15) << 2;
        float4 a = *(const float4*)&g_Q[(size_t)(qb + row) * EMB + c1 + (hh << 6) + c];
        unsigned h01, l01, h23, l23;
        split_pack(a.x*qscale, a.y*qscale, h01, l01);
        split_pack(a.z*qscale, a.w*qscale, h23, l23);
        int base = (hh*64 + row)*36 + (c >> 1);
        *(uint2*)&Qh[base] = make_uint2(h01, h23);
        *(uint2*)&Ql[base] = make_uint2(l01, l23);
    }

    // ---- prologue: prefetch first K/V tiles into registers ----
    float4 kq[8], vq[8];
    #pragma unroll
    for (int i = 0; i < 8; i++) {
        kq[i] = *(const float4*)&g_K[(size_t)(krow0 + (i << 3)) * EMB + c1 + (khh << 6) + kc0];
        vq[i] = *(const float4*)&g_V[(size_t)vrow * EMB + cv + ((vdg0 + (i << 2)) << 2)];
    }

    const unsigned* Qhh = Qh + sel*64*36;
    const unsigned* Qll = Ql + sel*64*36;
    const unsigned* Khh = Kh + sel*64*36;
    const unsigned* Kll = Kl + sel*64*36;
    float*          Ph  = Ps + sel*64*68;

    float O[2][8][4];                     // [head][nt][frag]
    #pragma unroll
    for (int hh = 0; hh < 2; hh++)
        #pragma unroll
        for (int nt = 0; nt < 8; nt++)
            #pragma unroll
            for (int q = 0; q < 4; q++) O[hh][nt][q] = 0.f;

    float m_lo = -1e30f, m_hi = -1e30f, l_lo = 0.f, l_hi = 0.f;

    for (int kb = 0; kb < SQ; kb += 64) {
        __syncthreads();                  // prev PV done before overwriting K/Vt
        // ---- split + store prefetched K tiles (both heads) ----
        #pragma unroll
        for (int i = 0; i < 8; i++) {
            int row = krow0 + (i << 3);
            unsigned h01, l01, h23, l23;
            split_pack(kq[i].x, kq[i].y, h01, l01);
            split_pack(kq[i].z, kq[i].w, h23, l23);
            int base = (khh*64 + row)*36 + (kc0 >> 1);
            *(uint2*)&Kh[base] = make_uint2(h01, h23);
            *(uint2*)&Kl[base] = make_uint2(l01, l23);
        }
        // ---- store prefetched V transposed + tf32-round ----
        #pragma unroll
        for (int i = 0; i < 8; i++) {
            int dg = vdg0 + (i << 2);
            Vt[(dg*4+0)*68 + vrow] = __uint_as_float(f2tf(vq[i].x));
            Vt[(dg*4+1)*68 + vrow] = __uint_as_float(f2tf(vq[i].y));
            Vt[(dg*4+2)*68 + vrow] = __uint_as_float(f2tf(vq[i].z));
            Vt[(dg*4+3)*68 + vrow] = __uint_as_float(f2tf(vq[i].w));
        }
        __syncthreads();

        // ---- prefetch next K/V tiles (latency hidden behind S+softmax+PV) ----
        if (kb + 64 < SQ) {
            #pragma unroll
            for (int i = 0; i < 8; i++) {
                kq[i] = *(const float4*)&g_K[(size_t)(kb + 64 + krow0 + (i << 3)) * EMB
                                             + c1 + (khh << 6) + kc0];
                vq[i] = *(const float4*)&g_V[(size_t)(kb + 64 + vrow) * EMB
                                             + cv + ((vdg0 + (i << 2)) << 2)];
            }
        }

        // ---- S = Q_sel K_sel^T  (16 rows x 64 keys), bf16x3 k16 ----
        float sacc[8][4];
        #pragma unroll
        for (int nt = 0; nt < 8; nt++)
            #pragma unroll
            for (int q = 0; q < 4; q++) sacc[nt][q] = 0.f;

        #pragma unroll
        for (int ks = 0; ks < 4; ks++) {  // 4 x k16 chunks over 64 dims
            const int kc = ks << 3;       // pair offset
            unsigned ah[4], al[4];
            ah[0] = Qhh[r_lo*36 + kc + t4];
            ah[1] = Qhh[r_hi*36 + kc + t4];
            ah[2] = Qhh[r_lo*36 + kc + t4 + 4];
            ah[3] = Qhh[r_hi*36 + kc + t4 + 4];
            al[0] = Qll[r_lo*36 + kc + t4];
            al[1] = Qll[r_hi*36 + kc + t4];
            al[2] = Qll[r_lo*36 + kc + t4 + 4];
            al[3] = Qll[r_hi*36 + kc + t4 + 4];
            #pragma unroll
            for (int nt = 0; nt < 8; nt++) {
                unsigned bh[2], bl[2];
                bh[0] = Khh[(nt*8+grp)*36 + kc + t4];
                bh[1] = Khh[(nt*8+grp)*36 + kc + t4 + 4];
                bl[0] = Kll[(nt*8+grp)*36 + kc + t4];
                bl[1] = Kll[(nt*8+grp)*36 + kc + t4 + 4];
                mma_bf16(sacc[nt], ah, bh);
                mma_bf16(sacc[nt], ah, bl);
                mma_bf16(sacc[nt], al, bh);
            }
        }

        // ---- online softmax (rows r_lo via c0/c1, r_hi via c2/c3) ----
        float mx_lo = -1e30f, mx_hi = -1e30f;
        #pragma unroll
        for (int nt = 0; nt < 8; nt++) {
            mx_lo = fmaxf(mx_lo, fmaxf(sacc[nt][0], sacc[nt][1]));
            mx_hi = fmaxf(mx_hi, fmaxf(sacc[nt][2], sacc[nt][3]));
        }
        mx_lo = fmaxf(mx_lo, __shfl_xor_sync(0xffffffffu, mx_lo, 1));
        mx_lo = fmaxf(mx_lo, __shfl_xor_sync(0xffffffffu, mx_lo, 2));
        mx_hi = fmaxf(mx_hi, __shfl_xor_sync(0xffffffffu, mx_hi, 1));
        mx_hi = fmaxf(mx_hi, __shfl_xor_sync(0xffffffffu, mx_hi, 2));
        const float mn_lo = fmaxf(m_lo, mx_lo);
        const float mn_hi = fmaxf(m_hi, mx_hi);
        const float sc_lo = __expf(m_lo - mn_lo);
        const float sc_hi = __expf(m_hi - mn_hi);
        float rs_lo = 0.f, rs_hi = 0.f;
        #pragma unroll
        for (int nt = 0; nt < 8; nt++) {
            float p0 = __expf(sacc[nt][0] - mn_lo);
            float p1 = __expf(sacc[nt][1] - mn_lo);
            float p2 = __expf(sacc[nt][2] - mn_hi);
            float p3 = __expf(sacc[nt][3] - mn_hi);
            rs_lo += p0 + p1;
            rs_hi += p2 + p3;
            int col = nt*8 + (t4 << 1);
            *(float2*)&Ph[r_lo*68 + col] =
                make_float2(__uint_as_float(f2tf(p0)), __uint_as_float(f2tf(p1)));
            *(float2*)&Ph[r_hi*68 + col] =
                make_float2(__uint_as_float(f2tf(p2)), __uint_as_float(f2tf(p3)));
        }
        rs_lo += __shfl_xor_sync(0xffffffffu, rs_lo, 1);
        rs_lo += __shfl_xor_sync(0xffffffffu, rs_lo, 2);
        rs_hi += __shfl_xor_sync(0xffffffffu, rs_hi, 1);
        rs_hi += __shfl_xor_sync(0xffffffffu, rs_hi, 2);
        l_lo = l_lo * sc_lo + rs_lo;  m_lo = mn_lo;
        l_hi = l_hi * sc_hi + rs_hi;  m_hi = mn_hi;
        if (t4 == 0) {
            scs[sel*64 + r_lo] = sc_lo;
            scs[sel*64 + r_hi] = sc_hi;
        }
        __syncthreads();

        // ---- PV: O[head] += P[head] * V  (1xTF32, this warp's V-half = sel) ----
        const float s1lo = scs[r_lo],      s1hi = scs[r_hi];
        const float s2lo = scs[64 + r_lo], s2hi = scs[64 + r_hi];
        #pragma unroll
        for (int hh = 0; hh < 2; hh++) {
            const float flo = hh ? s2lo : s1lo;
            const float fhi = hh ? s2hi : s1hi;
            #pragma unroll
            for (int nt = 0; nt < 8; nt++) {
                O[hh][nt][0] *= flo; O[hh][nt][1] *= flo;
                O[hh][nt][2] *= fhi; O[hh][nt][3] *= fhi;
            }
            const float* Pg = Ps + hh*64*68;
            #pragma unroll
            for (int ks = 0; ks < 8; ks++) {
                const int kc = ks << 3;
                unsigned a[4];
                a[0] = __float_as_uint(Pg[r_lo*68 + kc + t4]);
                a[1] = __float_as_uint(Pg[r_hi*68 + kc + t4]);
                a[2] = __float_as_uint(Pg[r_lo*68 + kc + t4 + 4]);
                a[3] = __float_as_uint(Pg[r_hi*68 + kc + t4 + 4]);
                #pragma unroll
                for (int nt = 0; nt < 8; nt++) {
                    unsigned b[2];
                    b[0] = __float_as_uint(Vt[(sel*64 + nt*8 + grp)*68 + kc + t4]);
                    b[1] = __float_as_uint(Vt[(sel*64 + nt*8 + grp)*68 + kc + t4 + 4]);
                    mma_tf32(O[hh][nt], a, b);
                }
            }
        }
    }

    // ---- epilogue: combine heads, RMSNorm over 128 dims, gain, scale ----
    if (t4 == 0) {
        ls[sel*64 + r_lo] = l_lo;
        ls[sel*64 + r_hi] = l_hi;
    }
    __syncthreads();
    const float lam   = g_lam;
    const float i1lo  = 1.f  / ls[r_lo],      i1hi = 1.f  / ls[r_hi];
    const float i2lo  = lam  / ls[64 + r_lo], i2hi = lam  / ls[64 + r_hi];
    float o[8][4], ss_lo = 0.f, ss_hi = 0.f;
    #pragma unroll
    for (int nt = 0; nt < 8; nt++) {
        o[nt][0] = O[0][nt][0]*i1lo - O[1][nt][0]*i2lo;
        o[nt][1] = O[0][nt][1]*i1lo - O[1][nt][1]*i2lo;
        o[nt][2] = O[0][nt][2]*i1hi - O[1][nt][2]*i2hi;
        o[nt][3] = O[0][nt][3]*i1hi - O[1][nt][3]*i2hi;
        ss_lo += o[nt][0]*o[nt][0] + o[nt][1]*o[nt][1];
        ss_hi += o[nt][2]*o[nt][2] + o[nt][3]*o[nt][3];
    }
    ss_lo += __shfl_xor_sync(0xffffffffu, ss_lo, 1);
    ss_lo += __shfl_xor_sync(0xffffffffu, ss_lo, 2);
    ss_hi += __shfl_xor_sync(0xffffffffu, ss_hi, 1);
    ss_hi += __shfl_xor_sync(0xffffffffu, ss_hi, 2);
    if (t4 == 0) {
        atomicAdd(&rss[r_lo], ss_lo);
        atomicAdd(&rss[r_hi], ss_hi);
    }
    __syncthreads();
    const float post_lo = rsqrtf(rss[r_lo] * (1.f/128.f) + 1e-5f) * (1.f - LAMBDA_INIT_F);
    const float post_hi = rsqrtf(rss[r_hi] * (1.f/128.f) + 1e-5f) * (1.f - LAMBDA_INIT_F);
    #pragma unroll
    for (int nt = 0; nt < 8; nt++) {
        int col = (sel << 6) + nt*8 + (t4 << 1);
        float g0 = gw[col], g1 = gw[col + 1];
        *(float2*)&g_A[(size_t)(qb + r_lo) * EMB + cv + col] =
            make_float2(o[nt][0]*post_lo*g0, o[nt][1]*post_lo*g1);
        *(float2*)&g_A[(size_t)(qb + r_hi) * EMB + cv + col] =
            make_float2(o[nt][2]*post_hi*g0, o[nt][3]*post_hi*g1);
    }
}

// ---------------------------------------------------------------------------
// kernel_launch
// ---------------------------------------------------------------------------
extern "C" void kernel_launch(void* const* d_in, const int* in_sizes, int n_in,
                              void* d_out, int out_size)
{
    const float* query = (const float*)d_in[0];
    const float* key_  = (const float*)d_in[1];
    const float* value = (const float*)d_in[2];
    // d_in[3] rel_pos, d_in[4] attn_mask — both no-ops here
    const float* Wq = (const float*)d_in[5];
    const float* Wk = (const float*)d_in[6];
    const float* Wv = (const float*)d_in[7];
    const float* Wo = (const float*)d_in[8];
    const float* lq1 = (const float*)d_in[9];
    const float* lk1 = (const float*)d_in[10];
    const float* lq2 = (const float*)d_in[11];
    const float* lk2 = (const float*)d_in[12];
    const float* gw  = (const float*)d_in[13];
    float* out = (float*)d_out;

    float *pQ, *pK, *pV, *pA;
    cudaGetSymbolAddress((void**)&pQ, g_Q);
    cudaGetSymbolAddress((void**)&pK, g_K);
    cudaGetSymbolAddress((void**)&pV, g_V);
    cudaGetSymbolAddress((void**)&pA, g_A);

    cudaFuncSetAttribute(gemm_bf16x3,
                         cudaFuncAttributeMaxDynamicSharedMemorySize, GEMM_SMEM_BYTES);
    cudaFuncSetAttribute(diffattn_tc,
                         cudaFuncAttributeMaxDynamicSharedMemorySize, ATT_SMEM_BYTES);

    lam_kernel<<<1, 32>>>(lq1, lk1, lq2, lk2);

    dim3 ggrid(SQ / 128, SQ / 128);
    gemm_bf16x3<<<ggrid, 256, GEMM_SMEM_BYTES>>>(query, Wq, pQ);
    gemm_bf16x3<<<ggrid, 256, GEMM_SMEM_BYTES>>>(key_,  Wk, pK);
    gemm_bf16x3<<<ggrid, 256, GEMM_SMEM_BYTES>>>(value, Wv, pV);

    dim3 agrid(SQ / 64, NH);
    diffattn_tc<<<agrid, 256, ATT_SMEM_BYTES>>>(gw);

    gemm_bf16x3<<<ggrid, 256, GEMM_SMEM_BYTES>>>(pA, Wo, out);
}